// round 5
// baseline (speedup 1.0000x reference)
#include <cuda_runtime.h>
#include <cuda_bf16.h>

#define KCOLS 45
#define NL 5
#define NMAX 8192
#define FDIM 3
#define BDIM 3

// G-table over alpha: G_l(a) = sum_t w_t P_l(t) e^{-a t^2}, plus dG/da.
#define NODES 512
#define AMIN  (-3.25f)
#define AMAX  (3.25f)
#define HSTEP ((AMAX - AMIN) / (float)(NODES - 1))
#define INVH  ((float)(NODES - 1) / (AMAX - AMIN))
#define TABW  12   // [G0 G2 G4 G6 G8 | Gp0..Gp8 | pad pad]

#define NBLK   64                    // n's per mega-block
#define TPB    (NBLK * FDIM)         // 192 threads = tuples per block

__device__ float g_coef[KCOLS];
__device__ float g_Gtab[NODES * TABW];

__device__ __forceinline__ float ex2(float x) {
    float r;
    asm("ex2.approx.f32 %0, %1;" : "=f"(r) : "f"(x));
    return r;
}

// ---------------------------------------------------------------------------
// Build G table: one warp per alpha node; inline Legendre recurrence.
// Also writes SH normalization coefs (thread 0).
// ---------------------------------------------------------------------------
__global__ void gtab_kernel(const int* __restrict__ num_t_ptr) {
    int gtid = blockIdx.x * blockDim.x + threadIdx.x;
    int wid  = gtid >> 5;
    int lane = threadIdx.x & 31;

    if (gtid == 0) {
        int col = 0;
        for (int l = 0; l <= 8; l += 2) {
            for (int m = -l; m <= l; m++) {
                int ma = m < 0 ? -m : m;
                double r = 1.0;
                for (int q = l - ma + 1; q <= l + ma; q++) r *= (double)q;
                double nrm = sqrt((2.0 * l + 1.0) / (4.0 * 3.14159265358979323846) / r);
                double c = (ma == 0) ? nrm : nrm * 1.4142135623730951;
                g_coef[col++] = (float)c;
            }
        }
    }
    if (wid >= NODES) return;

    const float LOG2E = 1.4426950408889634f;
    float alpha = AMIN + (float)wid * HSTEP;
    float aL2 = -alpha * LOG2E;

    int num_t = *num_t_ptr;
    float inv_nm1 = (num_t > 1) ? 1.0f / (float)(num_t - 1) : 0.0f;
    float wbase = 1.0f / (float)num_t;

    const float recip[8] = {1.f, 0.5f, 1.f/3.f, 0.25f, 0.2f, 1.f/6.f, 1.f/7.f, 0.125f};

    float g[5]  = {0.f, 0.f, 0.f, 0.f, 0.f};
    float gp[5] = {0.f, 0.f, 0.f, 0.f, 0.f};

    for (int i = lane; i < num_t; i += 32) {
        float t = (float)i * inv_nm1;
        float w = (i == 0 || i == num_t - 1) ? 0.5f * wbase : wbase;
        float t2 = t * t;
        float P[9];
        P[0] = 1.0f; P[1] = t;
        #pragma unroll
        for (int n = 1; n < 8; n++)
            P[n + 1] = ((2.0f * n + 1.0f) * t * P[n] - (float)n * P[n - 1]) * recip[n];
        float e = ex2(aL2 * t2);
        float we    = w * e;
        float wmet2 = -we * t2;
        #pragma unroll
        for (int l = 0; l < 5; l++) {
            g[l]  = fmaf(we,    P[2 * l], g[l]);
            gp[l] = fmaf(wmet2, P[2 * l], gp[l]);
        }
    }

    #pragma unroll
    for (int off = 16; off >= 1; off >>= 1) {
        #pragma unroll
        for (int l = 0; l < 5; l++) {
            g[l]  += __shfl_xor_sync(0xffffffffu, g[l],  off);
            gp[l] += __shfl_xor_sync(0xffffffffu, gp[l], off);
        }
    }

    if (lane == 0) {
        float* o = &g_Gtab[wid * TABW];
        #pragma unroll
        for (int l = 0; l < 5; l++) { o[l] = g[l]; o[5 + l] = gp[l]; }
        o[10] = 0.f; o[11] = 0.f;
    }
}

// ---------------------------------------------------------------------------
// Hermite cubic interpolation of all 5 G_l at scalar alpha, from smem table.
// ---------------------------------------------------------------------------
__device__ __forceinline__ void hermite5(const float* __restrict__ stab,
                                         float a, float* __restrict__ out) {
    float u = (a - AMIN) * INVH;
    u = fminf(fmaxf(u, 0.0f), (float)(NODES - 1) - 1e-4f);
    int j = (int)u;
    float f  = u - (float)j;
    float f2 = f * f;
    float fm = f - 1.0f;
    float h01 = f2 * (3.0f - 2.0f * f);
    float h00 = 1.0f - h01;
    float h10 = (f * fm * fm) * HSTEP;
    float h11 = (f2 * fm) * HSTEP;
    const float* n0 = stab + j * TABW;
    const float* n1 = n0 + TABW;
    #pragma unroll
    for (int l = 0; l < 5; l++)
        out[l] = fmaf(h00, n0[l], fmaf(h01, n1[l],
                 fmaf(h10, n0[5 + l], h11 * n1[5 + l])));
}

// ---------------------------------------------------------------------------
// Mega kernel: per block of 64 n's — SH + rho lookup into smem, then emit
// odf / ev / S as three contiguous coalesced chunks.
// Dynamic smem layout (floats):
//   [0, 6144)           G table (NODES*TABW)
//   [6144, 6144+8640)   odf_s[tuple][45]
//   [+8640, +2880)      rho_s[tuple][15]   ([b][l])
//   [+2880, +192)       w_s[tuple]
// ---------------------------------------------------------------------------
__global__ void __launch_bounds__(TPB)
mega_kernel(const float* __restrict__ dirs,
            const float* __restrict__ weights,
            const float4* __restrict__ shapes,
            float* __restrict__ S,
            float* __restrict__ odf,
            float* __restrict__ ev,
            int N) {
    extern __shared__ float sm[];
    float* stab  = sm;                        // 6144
    float* odf_s = stab + NODES * TABW;       // TPB*45 = 8640
    float* rho_s = odf_s + TPB * KCOLS;       // TPB*15 = 2880
    float* w_s   = rho_s + TPB * NL * BDIM;   // TPB

    int tid = threadIdx.x;
    int n0  = blockIdx.x * NBLK;
    int nloc = N - n0; if (nloc > NBLK) nloc = NBLK;
    int ntup = nloc * FDIM;

    for (int i = tid; i < NODES * TABW; i += TPB)
        stab[i] = g_Gtab[i];

    if (tid < ntup) {
        int tuple = n0 * FDIM + tid;

        // ---- weights ----
        w_s[tid] = __ldg(&weights[tuple]);

        // ---- SH basis ----
        {
            float x = dirs[tuple * 3 + 0];
            float y = dirs[tuple * 3 + 1];
            float z = dirs[tuple * 3 + 2];
            float inv = rsqrtf(x * x + y * y + z * z);
            x *= inv; y *= inv; z *= inv;

            float s2 = fminf(fmaxf(1.0f - z * z, 0.0f), 1.0f);
            float s = sqrtf(s2);

            float rxy = sqrtf(x * x + y * y);
            bool  havexy = rxy > 0.0f;
            float invr = havexy ? (1.0f / rxy) : 0.0f;
            float cphi = havexy ? x * invr : 1.0f;
            float sphi = y * invr;

            float* val = &odf_s[tid * KCOLS];
            const int base[5] = {0, 1, 6, 15, 28};

#define SH_EMIT(L, M, Pv)                                                    \
            {                                                                \
                int bi = base[(L) >> 1];                                    \
                float cf = g_coef[bi + (L) + (M)];                          \
                if ((M) == 0) {                                             \
                    val[bi + (L)] = cf * (Pv);                              \
                } else {                                                    \
                    val[bi + (L) + (M)] = cf * (Pv) * cm;                   \
                    val[bi + (L) - (M)] = cf * (Pv) * sm_;                  \
                }                                                            \
            }

            float pmm = 1.0f;
            float cm = 1.0f, sm_ = 0.0f;
            #pragma unroll
            for (int m = 0; m <= 8; m++) {
                float p_prev = pmm;
                if ((m & 1) == 0) SH_EMIT(m, m, p_prev);
                if (m < 8) {
                    float p_cur = (2.0f * m + 1.0f) * z * p_prev;
                    if (((m + 1) & 1) == 0) SH_EMIT(m + 1, m, p_cur);
                    #pragma unroll
                    for (int l = m + 2; l <= 8; l++) {
                        float p_next = ((2.0f * l - 1.0f) * z * p_cur -
                                        (float)(l + m - 1) * p_prev) / (float)(l - m);
                        p_prev = p_cur; p_cur = p_next;
                        if ((l & 1) == 0) SH_EMIT(l, m, p_cur);
                    }
                }
                pmm = -(2.0f * m + 1.0f) * s * pmm;
                float cn = cm * cphi - sm_ * sphi;
                float sn = sm_ * cphi + cm * sphi;
                cm = cn; sm_ = sn;
            }
#undef SH_EMIT
        }

        // ---- rho lookup (needs stab; loads above are same-warp ordered
        //      only after syncthreads, so do it after the barrier) ----
    }
    __syncthreads();

    if (tid < ntup) {
        int tuple = n0 * FDIM + tid;
        float4 sp = __ldg(&shapes[tuple]);   // {D_a, D_epar, D_eperp, z}
        float Da = sp.x;
        float dd = sp.y - sp.z;
        float z = sp.w, omz = 1.0f - z;
        const float LOG2E = 1.4426950408889634f;
        float e1 = ex2(-sp.z * LOG2E);

        float* o = &rho_s[tid * (NL * BDIM)];
        float eb = 1.0f;
        #pragma unroll
        for (int b = 1; b <= 3; b++) {
            eb *= e1;
            float Ga[5], Gc[5];
            hermite5(stab, (float)b * Da, Ga);
            hermite5(stab, (float)b * dd, Gc);
            float c2 = omz * eb;
            #pragma unroll
            for (int l = 0; l < 5; l++)
                o[(b - 1) * NL + l] = fmaf(z, Ga[l], c2 * Gc[l]);
        }
    }
    __syncthreads();

    // ---- emit odf: contiguous [n0*135, n0*135 + ntup*45) ----
    {
        float* dst = odf + (size_t)n0 * FDIM * KCOLS;
        int total = ntup * KCOLS;
        for (int i = tid; i < total; i += TPB) dst[i] = odf_s[i];
    }

    // ---- emit ev: ev[n][b][f][k] = rho_s[(n_loc*3+f)*15 + b*5 + lidx(k)] ----
    {
        float* dst = ev + (size_t)n0 * BDIM * FDIM * KCOLS;
        int total = nloc * BDIM * FDIM * KCOLS;   // nloc*405
        for (int i = tid; i < total; i += TPB) {
            int nl = i / (BDIM * FDIM * KCOLS);
            int r  = i - nl * (BDIM * FDIM * KCOLS);
            int b  = r / (FDIM * KCOLS);
            int r2 = r - b * (FDIM * KCOLS);
            int f  = r2 / KCOLS;
            int k  = r2 - f * KCOLS;
            int li = (k >= 28) ? 4 : ((k >= 15) ? 3 : ((k >= 6) ? 2 : ((k >= 1) ? 1 : 0)));
            dst[i] = rho_s[(nl * FDIM + f) * (NL * BDIM) + b * NL + li];
        }
    }

    // ---- emit S: S[n][b][k] = sum_f w*rho*odf ----
    {
        float* dst = S + (size_t)n0 * BDIM * KCOLS;
        int total = nloc * BDIM * KCOLS;          // nloc*135
        for (int i = tid; i < total; i += TPB) {
            int nl = i / (BDIM * KCOLS);
            int r  = i - nl * (BDIM * KCOLS);
            int b  = r / KCOLS;
            int k  = r - b * KCOLS;
            int li = (k >= 28) ? 4 : ((k >= 15) ? 3 : ((k >= 6) ? 2 : ((k >= 1) ? 1 : 0)));
            float acc = 0.0f;
            #pragma unroll
            for (int f = 0; f < FDIM; f++) {
                int tu = nl * FDIM + f;
                float e = rho_s[tu * (NL * BDIM) + b * NL + li];
                acc = fmaf(w_s[tu] * e, odf_s[tu * KCOLS + k], acc);
            }
            dst[i] = acc;
        }
    }
}

// ---------------------------------------------------------------------------
extern "C" void kernel_launch(void* const* d_in, const int* in_sizes, int n_in,
                              void* d_out, int out_size) {
    const float* directs = (const float*)d_in[0];  // (N, F, 3)
    const float* weights = (const float*)d_in[1];  // (N, F)
    const float* shapes  = (const float*)d_in[2];  // (N, F, 4)
    const int*   num_t   = (const int*)d_in[3];    // scalar

    int N = in_sizes[0] / (FDIM * 3);
    if (N > NMAX) N = NMAX;

    float* out = (float*)d_out;
    float* S   = out;                                   // (N, B, 45)
    float* odf = out + (size_t)N * BDIM * KCOLS;        // (N, F, 45)
    float* ev  = odf + (size_t)N * FDIM * KCOLS;        // (N, B, F, 45)

    gtab_kernel<<<(NODES * 32 + 255) / 256, 256>>>(num_t);

    const int smem_bytes = (NODES * TABW + TPB * KCOLS + TPB * NL * BDIM + TPB) * 4;
    static_assert((NODES * TABW + TPB * KCOLS + TPB * NL * BDIM + TPB) * 4 < 100 * 1024, "smem");
    cudaFuncSetAttribute(mega_kernel, cudaFuncAttributeMaxDynamicSharedMemorySize, smem_bytes);

    int nblocks = (N + NBLK - 1) / NBLK;
    mega_kernel<<<nblocks, TPB, smem_bytes>>>(directs, weights,
                                              (const float4*)shapes,
                                              S, odf, ev, N);
}

// round 6
// speedup vs baseline: 1.1274x; 1.1274x over previous
#include <cuda_runtime.h>
#include <cuda_bf16.h>

#define KCOLS 45
#define NL 5
#define NMAX 8192
#define FDIM 3
#define BDIM 3

// G-table over alpha: G_l(a) = sum_t w_t P_l(t) e^{-a t^2}, plus dG/da.
#define NODES 512
#define AMIN  (-3.25f)
#define AMAX  (3.25f)
#define HSTEP ((AMAX - AMIN) / (float)(NODES - 1))
#define INVH  ((float)(NODES - 1) / (AMAX - AMIN))
#define TABW  12   // [G0 G2 G4 G6 G8 | Gp0..Gp8 | pad pad]

#define NBLK   16                    // n's per mega-block
#define NTUP   (NBLK * FDIM)         // 48 tuples per block
#define TPB    256                   // threads per block

__device__ float g_coef[KCOLS];
__device__ float g_Gtab[NODES * TABW];

__device__ __forceinline__ float ex2(float x) {
    float r;
    asm("ex2.approx.f32 %0, %1;" : "=f"(r) : "f"(x));
    return r;
}

__device__ __forceinline__ int lidx(int k) {
    return (k >= 1) + (k >= 6) + (k >= 15) + (k >= 28);
}

// ---------------------------------------------------------------------------
// Build G table: one warp per alpha node; inline Legendre recurrence.
// Also writes SH normalization coefs (thread 0).
// ---------------------------------------------------------------------------
__global__ void gtab_kernel(const int* __restrict__ num_t_ptr) {
    int gtid = blockIdx.x * blockDim.x + threadIdx.x;
    int wid  = gtid >> 5;
    int lane = threadIdx.x & 31;

    if (gtid == 0) {
        int col = 0;
        for (int l = 0; l <= 8; l += 2) {
            for (int m = -l; m <= l; m++) {
                int ma = m < 0 ? -m : m;
                double r = 1.0;
                for (int q = l - ma + 1; q <= l + ma; q++) r *= (double)q;
                double nrm = sqrt((2.0 * l + 1.0) / (4.0 * 3.14159265358979323846) / r);
                double c = (ma == 0) ? nrm : nrm * 1.4142135623730951;
                g_coef[col++] = (float)c;
            }
        }
    }
    if (wid >= NODES) return;

    const float LOG2E = 1.4426950408889634f;
    float alpha = AMIN + (float)wid * HSTEP;
    float aL2 = -alpha * LOG2E;

    int num_t = *num_t_ptr;
    float inv_nm1 = (num_t > 1) ? 1.0f / (float)(num_t - 1) : 0.0f;
    float wbase = 1.0f / (float)num_t;

    const float recip[8] = {1.f, 0.5f, 1.f/3.f, 0.25f, 0.2f, 1.f/6.f, 1.f/7.f, 0.125f};

    float g[5]  = {0.f, 0.f, 0.f, 0.f, 0.f};
    float gp[5] = {0.f, 0.f, 0.f, 0.f, 0.f};

    for (int i = lane; i < num_t; i += 32) {
        float t = (float)i * inv_nm1;
        float w = (i == 0 || i == num_t - 1) ? 0.5f * wbase : wbase;
        float t2 = t * t;
        float P[9];
        P[0] = 1.0f; P[1] = t;
        #pragma unroll
        for (int n = 1; n < 8; n++)
            P[n + 1] = ((2.0f * n + 1.0f) * t * P[n] - (float)n * P[n - 1]) * recip[n];
        float e = ex2(aL2 * t2);
        float we    = w * e;
        float wmet2 = -we * t2;
        #pragma unroll
        for (int l = 0; l < 5; l++) {
            g[l]  = fmaf(we,    P[2 * l], g[l]);
            gp[l] = fmaf(wmet2, P[2 * l], gp[l]);
        }
    }

    #pragma unroll
    for (int off = 16; off >= 1; off >>= 1) {
        #pragma unroll
        for (int l = 0; l < 5; l++) {
            g[l]  += __shfl_xor_sync(0xffffffffu, g[l],  off);
            gp[l] += __shfl_xor_sync(0xffffffffu, gp[l], off);
        }
    }

    if (lane == 0) {
        float* o = &g_Gtab[wid * TABW];
        #pragma unroll
        for (int l = 0; l < 5; l++) { o[l] = g[l]; o[5 + l] = gp[l]; }
        o[10] = 0.f; o[11] = 0.f;
    }
}

// ---------------------------------------------------------------------------
// Hermite cubic interpolation of all 5 G_l at scalar alpha, from smem table.
// ---------------------------------------------------------------------------
__device__ __forceinline__ void hermite5(const float* __restrict__ stab,
                                         float a, float* __restrict__ out) {
    float u = (a - AMIN) * INVH;
    u = fminf(fmaxf(u, 0.0f), (float)(NODES - 1) - 1e-4f);
    int j = (int)u;
    float f  = u - (float)j;
    float f2 = f * f;
    float fm = f - 1.0f;
    float h01 = f2 * (3.0f - 2.0f * f);
    float h00 = 1.0f - h01;
    float h10 = (f * fm * fm) * HSTEP;
    float h11 = (f2 * fm) * HSTEP;
    const float* n0 = stab + j * TABW;
    const float* n1 = n0 + TABW;
    #pragma unroll
    for (int l = 0; l < 5; l++)
        out[l] = fmaf(h00, n0[l], fmaf(h01, n1[l],
                 fmaf(h10, n0[5 + l], h11 * n1[5 + l])));
}

// ---------------------------------------------------------------------------
// Mega kernel: block of 16 n's (48 tuples). SH + rho in smem, then emit
// odf / ev / S as contiguous float4 chunks.
// smem (floats): stab 6144 | odf_s 48*45=2160 | rho_s 48*15=720 | w_s 48
// total = 9072 floats = 36.3 KB
// ---------------------------------------------------------------------------
__global__ void __launch_bounds__(TPB)
mega_kernel(const float* __restrict__ dirs,
            const float* __restrict__ weights,
            const float4* __restrict__ shapes,
            float* __restrict__ S,
            float* __restrict__ odf,
            float* __restrict__ ev,
            int N) {
    extern __shared__ float sm[];
    float* stab  = sm;                        // 6144
    float* odf_s = stab + NODES * TABW;       // 2160
    float* rho_s = odf_s + NTUP * KCOLS;      // 720
    float* w_s   = rho_s + NTUP * NL * BDIM;  // 48

    int tid = threadIdx.x;
    int n0  = blockIdx.x * NBLK;
    int nloc = N - n0; if (nloc > NBLK) nloc = NBLK;
    int ntup = nloc * FDIM;

    // stab load (float4, coalesced): 1536 float4 / 256 thr = 6 each
    {
        const float4* src = (const float4*)g_Gtab;
        float4* dst = (float4*)stab;
        #pragma unroll
        for (int i = tid; i < NODES * TABW / 4; i += TPB) dst[i] = src[i];
    }

    if (tid < ntup) {
        int tuple = n0 * FDIM + tid;
        w_s[tid] = __ldg(&weights[tuple]);

        // ---- SH basis ----
        float x = dirs[tuple * 3 + 0];
        float y = dirs[tuple * 3 + 1];
        float z = dirs[tuple * 3 + 2];
        float inv = rsqrtf(x * x + y * y + z * z);
        x *= inv; y *= inv; z *= inv;

        float s2 = fminf(fmaxf(1.0f - z * z, 0.0f), 1.0f);
        float s = sqrtf(s2);

        float rxy = sqrtf(x * x + y * y);
        bool  havexy = rxy > 0.0f;
        float invr = havexy ? (1.0f / rxy) : 0.0f;
        float cphi = havexy ? x * invr : 1.0f;
        float sphi = y * invr;

        float* val = &odf_s[tid * KCOLS];
        const int base[5] = {0, 1, 6, 15, 28};

#define SH_EMIT(L, M, Pv)                                                    \
        {                                                                    \
            int bi = base[(L) >> 1];                                        \
            float cf = g_coef[bi + (L) + (M)];                              \
            if ((M) == 0) {                                                 \
                val[bi + (L)] = cf * (Pv);                                  \
            } else {                                                        \
                val[bi + (L) + (M)] = cf * (Pv) * cm;                       \
                val[bi + (L) - (M)] = cf * (Pv) * sm_;                      \
            }                                                                \
        }

        float pmm = 1.0f;
        float cm = 1.0f, sm_ = 0.0f;
        #pragma unroll
        for (int m = 0; m <= 8; m++) {
            float p_prev = pmm;
            if ((m & 1) == 0) SH_EMIT(m, m, p_prev);
            if (m < 8) {
                float p_cur = (2.0f * m + 1.0f) * z * p_prev;
                if (((m + 1) & 1) == 0) SH_EMIT(m + 1, m, p_cur);
                #pragma unroll
                for (int l = m + 2; l <= 8; l++) {
                    float p_next = ((2.0f * l - 1.0f) * z * p_cur -
                                    (float)(l + m - 1) * p_prev) / (float)(l - m);
                    p_prev = p_cur; p_cur = p_next;
                    if ((l & 1) == 0) SH_EMIT(l, m, p_cur);
                }
            }
            pmm = -(2.0f * m + 1.0f) * s * pmm;
            float cn = cm * cphi - sm_ * sphi;
            float sn = sm_ * cphi + cm * sphi;
            cm = cn; sm_ = sn;
        }
#undef SH_EMIT
    }
    __syncthreads();   // stab + odf_s + w_s visible

    if (tid < ntup) {
        int tuple = n0 * FDIM + tid;
        float4 sp = __ldg(&shapes[tuple]);   // {D_a, D_epar, D_eperp, z}
        float Da = sp.x;
        float dd = sp.y - sp.z;
        float z = sp.w, omz = 1.0f - z;
        const float LOG2E = 1.4426950408889634f;
        float e1 = ex2(-sp.z * LOG2E);

        float* o = &rho_s[tid * (NL * BDIM)];
        float eb = 1.0f;
        #pragma unroll
        for (int b = 1; b <= 3; b++) {
            eb *= e1;
            float Ga[5], Gc[5];
            hermite5(stab, (float)b * Da, Ga);
            hermite5(stab, (float)b * dd, Gc);
            float c2 = omz * eb;
            #pragma unroll
            for (int l = 0; l < 5; l++)
                o[(b - 1) * NL + l] = fmaf(z, Ga[l], c2 * Gc[l]);
        }
    }
    __syncthreads();   // rho_s visible

    // ---- emit odf (float4) ----
    {
        int total = ntup * KCOLS;           // 2160 when full
        int nv = total >> 2;
        float4* dst = (float4*)(odf + (size_t)n0 * FDIM * KCOLS);
        const float4* src = (const float4*)odf_s;
        for (int i = tid; i < nv; i += TPB) dst[i] = src[i];
        for (int i = (nv << 2) + tid; i < total; i += TPB)
            odf[(size_t)n0 * FDIM * KCOLS + i] = odf_s[i];
    }

    // ---- emit ev (float4): ev[nl][b][f][k] = rho_s[(nl*3+f)*15 + b*5 + lidx(k)] ----
    {
        int total = nloc * BDIM * FDIM * KCOLS;   // 6480 when full
        int nv = total >> 2;
        float* dstb = ev + (size_t)n0 * BDIM * FDIM * KCOLS;
        float4* dst4 = (float4*)dstb;
        for (int i = tid; i < nv; i += TPB) {
            int e = i << 2;
            int row = e / KCOLS;                 // nl*9 + b*3 + f
            int k   = e - row * KCOLS;
            int f   = row % FDIM;
            int rb  = row / FDIM;
            int b   = rb % BDIM;
            int nl  = rb / BDIM;
            const float* rr = &rho_s[(nl * FDIM + f) * (NL * BDIM) + b * NL];
            float v[4];
            #pragma unroll
            for (int j = 0; j < 4; j++) {
                v[j] = rr[lidx(k)];
                if (++k == KCOLS) {              // row rolls over
                    k = 0;
                    if (++f == FDIM) { f = 0; if (++b == BDIM) { b = 0; nl++; } }
                    rr = &rho_s[(nl * FDIM + f) * (NL * BDIM) + b * NL];
                }
            }
            dst4[i] = make_float4(v[0], v[1], v[2], v[3]);
        }
        for (int e = (nv << 2) + tid; e < total; e += TPB) {
            int row = e / KCOLS;
            int k   = e - row * KCOLS;
            int f   = row % FDIM;
            int rb  = row / FDIM;
            int b   = rb % BDIM;
            int nl  = rb / BDIM;
            dstb[e] = rho_s[(nl * FDIM + f) * (NL * BDIM) + b * NL + lidx(k)];
        }
    }

    // ---- emit S (float4): S[nl][b][k] = sum_f w*rho*odf ----
    {
        int total = nloc * BDIM * KCOLS;          // 2160 when full
        int nv = total >> 2;
        float* dstb = S + (size_t)n0 * BDIM * KCOLS;
        float4* dst4 = (float4*)dstb;
        for (int i = tid; i < nv; i += TPB) {
            int e = i << 2;
            int row = e / KCOLS;                  // nl*3 + b
            int k   = e - row * KCOLS;
            int b   = row % BDIM;
            int nl  = row / BDIM;
            float v[4];
            #pragma unroll
            for (int j = 0; j < 4; j++) {
                int li = lidx(k);
                float acc = 0.0f;
                #pragma unroll
                for (int f = 0; f < FDIM; f++) {
                    int tu = nl * FDIM + f;
                    float rv = rho_s[tu * (NL * BDIM) + b * NL + li];
                    acc = fmaf(w_s[tu] * rv, odf_s[tu * KCOLS + k], acc);
                }
                v[j] = acc;
                if (++k == KCOLS) {
                    k = 0;
                    if (++b == BDIM) { b = 0; nl++; }
                }
            }
            dst4[i] = make_float4(v[0], v[1], v[2], v[3]);
        }
        for (int e = (nv << 2) + tid; e < total; e += TPB) {
            int row = e / KCOLS;
            int k   = e - row * KCOLS;
            int b   = row % BDIM;
            int nl  = row / BDIM;
            int li  = lidx(k);
            float acc = 0.0f;
            #pragma unroll
            for (int f = 0; f < FDIM; f++) {
                int tu = nl * FDIM + f;
                float rv = rho_s[tu * (NL * BDIM) + b * NL + li];
                acc = fmaf(w_s[tu] * rv, odf_s[tu * KCOLS + k], acc);
            }
            dstb[e] = acc;
        }
    }
}

// ---------------------------------------------------------------------------
extern "C" void kernel_launch(void* const* d_in, const int* in_sizes, int n_in,
                              void* d_out, int out_size) {
    const float* directs = (const float*)d_in[0];  // (N, F, 3)
    const float* weights = (const float*)d_in[1];  // (N, F)
    const float* shapes  = (const float*)d_in[2];  // (N, F, 4)
    const int*   num_t   = (const int*)d_in[3];    // scalar

    int N = in_sizes[0] / (FDIM * 3);
    if (N > NMAX) N = NMAX;

    float* out = (float*)d_out;
    float* S   = out;                                   // (N, B, 45)
    float* odf = out + (size_t)N * BDIM * KCOLS;        // (N, F, 45)
    float* ev  = odf + (size_t)N * FDIM * KCOLS;        // (N, B, F, 45)

    gtab_kernel<<<(NODES * 32 + 255) / 256, 256>>>(num_t);

    const int smem_bytes = (NODES * TABW + NTUP * KCOLS + NTUP * NL * BDIM + NTUP) * 4;
    cudaFuncSetAttribute(mega_kernel, cudaFuncAttributeMaxDynamicSharedMemorySize, smem_bytes);

    int nblocks = (N + NBLK - 1) / NBLK;
    mega_kernel<<<nblocks, TPB, smem_bytes>>>(directs, weights,
                                              (const float4*)shapes,
                                              S, odf, ev, N);
}

// round 7
// speedup vs baseline: 3.2008x; 2.8391x over previous
#include <cuda_runtime.h>
#include <cuda_bf16.h>

#define KCOLS 45
#define NL 5
#define NMAX 8192
#define FDIM 3
#define BDIM 3

// G-table over alpha: G_l(a) = sum_t w_t P_l(t) e^{-a t^2}, plus dG/da.
#define NODES 512
#define AMIN  (-3.25f)
#define AMAX  (3.25f)
#define HSTEP ((AMAX - AMIN) / (float)(NODES - 1))
#define INVH  ((float)(NODES - 1) / (AMAX - AMIN))
#define TABW  12   // [G0 G2 G4 G6 G8 | Gp0..Gp8 | pad pad]

#define NBLK   16                    // n's per mega-block
#define NTUP   (NBLK * FDIM)         // 48 tuples per block
#define TPB    256                   // threads per block

__device__ float g_coef[KCOLS];
__device__ float g_Gtab[NODES * TABW];

__device__ __forceinline__ float ex2(float x) {
    float r;
    asm("ex2.approx.f32 %0, %1;" : "=f"(r) : "f"(x));
    return r;
}

// ---------------------------------------------------------------------------
// Build G table: one warp per alpha node; inline Legendre recurrence.
// SH normalization coefs computed in PARALLEL (one thread per column) —
// the former serial thread-0 double-precision loop cost ~45us alone.
// ---------------------------------------------------------------------------
__global__ void gtab_kernel(const int* __restrict__ num_t_ptr) {
    int gtid = blockIdx.x * blockDim.x + threadIdx.x;
    int wid  = gtid >> 5;
    int lane = threadIdx.x & 31;

    if (gtid < KCOLS) {
        // col -> (l, m): bases {0,1,6,15,28} for l = 0,2,4,6,8
        int col = gtid;
        int l, base;
        if      (col >= 28) { l = 8; base = 28; }
        else if (col >= 15) { l = 6; base = 15; }
        else if (col >= 6)  { l = 4; base = 6;  }
        else if (col >= 1)  { l = 2; base = 1;  }
        else                { l = 0; base = 0;  }
        int m  = col - base - l;
        int ma = m < 0 ? -m : m;
        double r = 1.0;
        for (int q = l - ma + 1; q <= l + ma; q++) r *= (double)q;
        double nrm = sqrt((2.0 * l + 1.0) / (4.0 * 3.14159265358979323846) / r);
        double c = (ma == 0) ? nrm : nrm * 1.4142135623730951;
        g_coef[col] = (float)c;
    }
    if (wid >= NODES) return;

    const float LOG2E = 1.4426950408889634f;
    float alpha = AMIN + (float)wid * HSTEP;
    float aL2 = -alpha * LOG2E;

    int num_t = *num_t_ptr;
    float inv_nm1 = (num_t > 1) ? 1.0f / (float)(num_t - 1) : 0.0f;
    float wbase = 1.0f / (float)num_t;

    const float recip[8] = {1.f, 0.5f, 1.f/3.f, 0.25f, 0.2f, 1.f/6.f, 1.f/7.f, 0.125f};

    float g[5]  = {0.f, 0.f, 0.f, 0.f, 0.f};
    float gp[5] = {0.f, 0.f, 0.f, 0.f, 0.f};

    for (int i = lane; i < num_t; i += 32) {
        float t = (float)i * inv_nm1;
        float w = (i == 0 || i == num_t - 1) ? 0.5f * wbase : wbase;
        float t2 = t * t;
        float P[9];
        P[0] = 1.0f; P[1] = t;
        #pragma unroll
        for (int n = 1; n < 8; n++)
            P[n + 1] = ((2.0f * n + 1.0f) * t * P[n] - (float)n * P[n - 1]) * recip[n];
        float e = ex2(aL2 * t2);
        float we    = w * e;
        float wmet2 = -we * t2;
        #pragma unroll
        for (int l = 0; l < 5; l++) {
            g[l]  = fmaf(we,    P[2 * l], g[l]);
            gp[l] = fmaf(wmet2, P[2 * l], gp[l]);
        }
    }

    #pragma unroll
    for (int off = 16; off >= 1; off >>= 1) {
        #pragma unroll
        for (int l = 0; l < 5; l++) {
            g[l]  += __shfl_xor_sync(0xffffffffu, g[l],  off);
            gp[l] += __shfl_xor_sync(0xffffffffu, gp[l], off);
        }
    }

    if (lane == 0) {
        float* o = &g_Gtab[wid * TABW];
        #pragma unroll
        for (int l = 0; l < 5; l++) { o[l] = g[l]; o[5 + l] = gp[l]; }
        o[10] = 0.f; o[11] = 0.f;
    }
}

// ---------------------------------------------------------------------------
// Hermite cubic interpolation of all 5 G_l at scalar alpha, from smem table.
// ---------------------------------------------------------------------------
__device__ __forceinline__ void hermite5(const float* __restrict__ stab,
                                         float a, float* __restrict__ out) {
    float u = (a - AMIN) * INVH;
    u = fminf(fmaxf(u, 0.0f), (float)(NODES - 1) - 1e-4f);
    int j = (int)u;
    float f  = u - (float)j;
    float f2 = f * f;
    float fm = f - 1.0f;
    float h01 = f2 * (3.0f - 2.0f * f);
    float h00 = 1.0f - h01;
    float h10 = (f * fm * fm) * HSTEP;
    float h11 = (f2 * fm) * HSTEP;
    const float* n0 = stab + j * TABW;
    const float* n1 = n0 + TABW;
    #pragma unroll
    for (int l = 0; l < 5; l++)
        out[l] = fmaf(h00, n0[l], fmaf(h01, n1[l],
                 fmaf(h10, n0[5 + l], h11 * n1[5 + l])));
}

// ---------------------------------------------------------------------------
// Mega kernel: block of 16 n's (48 tuples). SH + rho in smem, then emit
// odf / ev / S as contiguous float4 chunks.
// smem (floats): stab 6144 | odf_s 2160 | rho_s 720 | w_s 48 | li_s 48(pad)
// ---------------------------------------------------------------------------
__global__ void __launch_bounds__(TPB)
mega_kernel(const float* __restrict__ dirs,
            const float* __restrict__ weights,
            const float4* __restrict__ shapes,
            float* __restrict__ S,
            float* __restrict__ odf,
            float* __restrict__ ev,
            int N) {
    extern __shared__ float sm[];
    float* stab  = sm;                        // 6144
    float* odf_s = stab + NODES * TABW;       // 2160
    float* rho_s = odf_s + NTUP * KCOLS;      // 720
    float* w_s   = rho_s + NTUP * NL * BDIM;  // 48
    int*   li_s  = (int*)(w_s + NTUP);        // 48 ints (KCOLS used)

    int tid = threadIdx.x;
    int n0  = blockIdx.x * NBLK;
    int nloc = N - n0; if (nloc > NBLK) nloc = NBLK;
    int ntup = nloc * FDIM;

    // stab load (float4, coalesced)
    {
        const float4* src = (const float4*)g_Gtab;
        float4* dst = (float4*)stab;
        #pragma unroll
        for (int i = tid; i < NODES * TABW / 4; i += TPB) dst[i] = src[i];
    }
    // lidx lookup table
    if (tid < KCOLS)
        li_s[tid] = (tid >= 1) + (tid >= 6) + (tid >= 15) + (tid >= 28);

    if (tid < ntup) {
        int tuple = n0 * FDIM + tid;
        w_s[tid] = __ldg(&weights[tuple]);

        // ---- SH basis ----
        float x = dirs[tuple * 3 + 0];
        float y = dirs[tuple * 3 + 1];
        float z = dirs[tuple * 3 + 2];
        float inv = rsqrtf(x * x + y * y + z * z);
        x *= inv; y *= inv; z *= inv;

        float s2 = fminf(fmaxf(1.0f - z * z, 0.0f), 1.0f);
        float s = sqrtf(s2);

        float rxy = sqrtf(x * x + y * y);
        bool  havexy = rxy > 0.0f;
        float invr = havexy ? (1.0f / rxy) : 0.0f;
        float cphi = havexy ? x * invr : 1.0f;
        float sphi = y * invr;

        float* val = &odf_s[tid * KCOLS];
        const int base[5] = {0, 1, 6, 15, 28};

#define SH_EMIT(L, M, Pv)                                                    \
        {                                                                    \
            int bi = base[(L) >> 1];                                        \
            float cf = g_coef[bi + (L) + (M)];                              \
            if ((M) == 0) {                                                 \
                val[bi + (L)] = cf * (Pv);                                  \
            } else {                                                        \
                val[bi + (L) + (M)] = cf * (Pv) * cm;                       \
                val[bi + (L) - (M)] = cf * (Pv) * sm_;                      \
            }                                                                \
        }

        float pmm = 1.0f;
        float cm = 1.0f, sm_ = 0.0f;
        #pragma unroll
        for (int m = 0; m <= 8; m++) {
            float p_prev = pmm;
            if ((m & 1) == 0) SH_EMIT(m, m, p_prev);
            if (m < 8) {
                float p_cur = (2.0f * m + 1.0f) * z * p_prev;
                if (((m + 1) & 1) == 0) SH_EMIT(m + 1, m, p_cur);
                #pragma unroll
                for (int l = m + 2; l <= 8; l++) {
                    float p_next = ((2.0f * l - 1.0f) * z * p_cur -
                                    (float)(l + m - 1) * p_prev) / (float)(l - m);
                    p_prev = p_cur; p_cur = p_next;
                    if ((l & 1) == 0) SH_EMIT(l, m, p_cur);
                }
            }
            pmm = -(2.0f * m + 1.0f) * s * pmm;
            float cn = cm * cphi - sm_ * sphi;
            float sn = sm_ * cphi + cm * sphi;
            cm = cn; sm_ = sn;
        }
#undef SH_EMIT
    }
    __syncthreads();   // stab + odf_s + w_s + li_s visible

    if (tid < ntup) {
        int tuple = n0 * FDIM + tid;
        float4 sp = __ldg(&shapes[tuple]);   // {D_a, D_epar, D_eperp, z}
        float Da = sp.x;
        float dd = sp.y - sp.z;
        float z = sp.w, omz = 1.0f - z;
        const float LOG2E = 1.4426950408889634f;
        float e1 = ex2(-sp.z * LOG2E);

        float* o = &rho_s[tid * (NL * BDIM)];
        float eb = 1.0f;
        #pragma unroll
        for (int b = 1; b <= 3; b++) {
            eb *= e1;
            float Ga[5], Gc[5];
            hermite5(stab, (float)b * Da, Ga);
            hermite5(stab, (float)b * dd, Gc);
            float c2 = omz * eb;
            #pragma unroll
            for (int l = 0; l < 5; l++)
                o[(b - 1) * NL + l] = fmaf(z, Ga[l], c2 * Gc[l]);
        }
    }
    __syncthreads();   // rho_s visible

    // ---- emit odf (float4) ----
    {
        int total = ntup * KCOLS;           // 2160 when full
        int nv = total >> 2;
        float4* dst = (float4*)(odf + (size_t)n0 * FDIM * KCOLS);
        const float4* src = (const float4*)odf_s;
        for (int i = tid; i < nv; i += TPB) dst[i] = src[i];
        for (int i = (nv << 2) + tid; i < total; i += TPB)
            odf[(size_t)n0 * FDIM * KCOLS + i] = odf_s[i];
    }

    // ---- emit ev (float4): ev[nl][b][f][k] = rho_s[(nl*3+f)*15 + b*5 + li_s[k]] ----
    {
        int total = nloc * BDIM * FDIM * KCOLS;   // 6480 when full
        int nv = total >> 2;
        float* dstb = ev + (size_t)n0 * BDIM * FDIM * KCOLS;
        float4* dst4 = (float4*)dstb;
        for (int i = tid; i < nv; i += TPB) {
            int e = i << 2;
            int row = e / KCOLS;                 // nl*9 + b*3 + f
            int k   = e - row * KCOLS;
            int f   = row % FDIM;
            int rb  = row / FDIM;
            int b   = rb % BDIM;
            int nl  = rb / BDIM;
            const float* rr = &rho_s[(nl * FDIM + f) * (NL * BDIM) + b * NL];
            float v[4];
            #pragma unroll
            for (int j = 0; j < 4; j++) {
                v[j] = rr[li_s[k]];
                if (++k == KCOLS) {
                    k = 0;
                    if (++f == FDIM) { f = 0; if (++b == BDIM) { b = 0; nl++; } }
                    rr = &rho_s[(nl * FDIM + f) * (NL * BDIM) + b * NL];
                }
            }
            dst4[i] = make_float4(v[0], v[1], v[2], v[3]);
        }
        for (int e = (nv << 2) + tid; e < total; e += TPB) {
            int row = e / KCOLS;
            int k   = e - row * KCOLS;
            int f   = row % FDIM;
            int rb  = row / FDIM;
            int b   = rb % BDIM;
            int nl  = rb / BDIM;
            dstb[e] = rho_s[(nl * FDIM + f) * (NL * BDIM) + b * NL + li_s[k]];
        }
    }

    // ---- emit S (float4): S[nl][b][k] = sum_f w*rho*odf ----
    {
        int total = nloc * BDIM * KCOLS;          // 2160 when full
        int nv = total >> 2;
        float* dstb = S + (size_t)n0 * BDIM * KCOLS;
        float4* dst4 = (float4*)dstb;
        for (int i = tid; i < nv; i += TPB) {
            int e = i << 2;
            int row = e / KCOLS;                  // nl*3 + b
            int k   = e - row * KCOLS;
            int b   = row % BDIM;
            int nl  = row / BDIM;
            float v[4];
            #pragma unroll
            for (int j = 0; j < 4; j++) {
                int li = li_s[k];
                float acc = 0.0f;
                #pragma unroll
                for (int f = 0; f < FDIM; f++) {
                    int tu = nl * FDIM + f;
                    float rv = rho_s[tu * (NL * BDIM) + b * NL + li];
                    acc = fmaf(w_s[tu] * rv, odf_s[tu * KCOLS + k], acc);
                }
                v[j] = acc;
                if (++k == KCOLS) {
                    k = 0;
                    if (++b == BDIM) { b = 0; nl++; }
                }
            }
            dst4[i] = make_float4(v[0], v[1], v[2], v[3]);
        }
        for (int e = (nv << 2) + tid; e < total; e += TPB) {
            int row = e / KCOLS;
            int k   = e - row * KCOLS;
            int b   = row % BDIM;
            int nl  = row / BDIM;
            int li  = li_s[k];
            float acc = 0.0f;
            #pragma unroll
            for (int f = 0; f < FDIM; f++) {
                int tu = nl * FDIM + f;
                float rv = rho_s[tu * (NL * BDIM) + b * NL + li];
                acc = fmaf(w_s[tu] * rv, odf_s[tu * KCOLS + k], acc);
            }
            dstb[e] = acc;
        }
    }
}

// ---------------------------------------------------------------------------
extern "C" void kernel_launch(void* const* d_in, const int* in_sizes, int n_in,
                              void* d_out, int out_size) {
    const float* directs = (const float*)d_in[0];  // (N, F, 3)
    const float* weights = (const float*)d_in[1];  // (N, F)
    const float* shapes  = (const float*)d_in[2];  // (N, F, 4)
    const int*   num_t   = (const int*)d_in[3];    // scalar

    int N = in_sizes[0] / (FDIM * 3);
    if (N > NMAX) N = NMAX;

    float* out = (float*)d_out;
    float* S   = out;                                   // (N, B, 45)
    float* odf = out + (size_t)N * BDIM * KCOLS;        // (N, F, 45)
    float* ev  = odf + (size_t)N * FDIM * KCOLS;        // (N, B, F, 45)

    gtab_kernel<<<(NODES * 32 + 255) / 256, 256>>>(num_t);

    const int smem_bytes = (NODES * TABW + NTUP * KCOLS + NTUP * NL * BDIM + NTUP + KCOLS + 3) * 4;
    cudaFuncSetAttribute(mega_kernel, cudaFuncAttributeMaxDynamicSharedMemorySize, smem_bytes);

    int nblocks = (N + NBLK - 1) / NBLK;
    mega_kernel<<<nblocks, TPB, smem_bytes>>>(directs, weights,
                                              (const float4*)shapes,
                                              S, odf, ev, N);
}

// round 8
// speedup vs baseline: 3.5419x; 1.1065x over previous
#include <cuda_runtime.h>
#include <cuda_bf16.h>

#define KCOLS 45
#define NL 5
#define NMAX 8192
#define FDIM 3
#define BDIM 3

// G-table over alpha: G_l(a) = sum_t w_t P_l(t) e^{-a t^2}, plus dG/da.
#define NODES 256
#define AMIN  (-3.25f)
#define AMAX  (3.25f)
#define HSTEP ((AMAX - AMIN) / (float)(NODES - 1))
#define INVH  ((float)(NODES - 1) / (AMAX - AMIN))
#define TABW  12   // per node: {G0,G2,G4,G6},{G8,Gp0,Gp2,Gp4},{Gp6,Gp8,0,0}

#define NBLK   16                    // n's per mega-block
#define NTUP   (NBLK * FDIM)         // 48 tuples per block
#define TPB    256                   // threads per block

__device__ float g_coef[KCOLS];
__device__ float g_Gtab[NODES * TABW];

__device__ __forceinline__ float ex2(float x) {
    float r;
    asm("ex2.approx.f32 %0, %1;" : "=f"(r) : "f"(x));
    return r;
}

// ---------------------------------------------------------------------------
// Build G table: one warp per alpha node; SH coefs in parallel (45 threads).
// ---------------------------------------------------------------------------
__global__ void gtab_kernel(const int* __restrict__ num_t_ptr) {
    int gtid = blockIdx.x * blockDim.x + threadIdx.x;
    int wid  = gtid >> 5;
    int lane = threadIdx.x & 31;

    if (gtid < KCOLS) {
        int col = gtid;
        int l, base;
        if      (col >= 28) { l = 8; base = 28; }
        else if (col >= 15) { l = 6; base = 15; }
        else if (col >= 6)  { l = 4; base = 6;  }
        else if (col >= 1)  { l = 2; base = 1;  }
        else                { l = 0; base = 0;  }
        int m  = col - base - l;
        int ma = m < 0 ? -m : m;
        double r = 1.0;
        for (int q = l - ma + 1; q <= l + ma; q++) r *= (double)q;
        double nrm = sqrt((2.0 * l + 1.0) / (4.0 * 3.14159265358979323846) / r);
        double c = (ma == 0) ? nrm : nrm * 1.4142135623730951;
        g_coef[col] = (float)c;
    }
    if (wid >= NODES) return;

    const float LOG2E = 1.4426950408889634f;
    float alpha = AMIN + (float)wid * HSTEP;
    float aL2 = -alpha * LOG2E;

    int num_t = *num_t_ptr;
    float inv_nm1 = (num_t > 1) ? 1.0f / (float)(num_t - 1) : 0.0f;
    float wbase = 1.0f / (float)num_t;

    const float recip[8] = {1.f, 0.5f, 1.f/3.f, 0.25f, 0.2f, 1.f/6.f, 1.f/7.f, 0.125f};

    float g[5]  = {0.f, 0.f, 0.f, 0.f, 0.f};
    float gp[5] = {0.f, 0.f, 0.f, 0.f, 0.f};

    #pragma unroll 2
    for (int i = lane; i < num_t; i += 32) {
        float t = (float)i * inv_nm1;
        float w = (i == 0 || i == num_t - 1) ? 0.5f * wbase : wbase;
        float t2 = t * t;
        float P[9];
        P[0] = 1.0f; P[1] = t;
        #pragma unroll
        for (int n = 1; n < 8; n++)
            P[n + 1] = ((2.0f * n + 1.0f) * t * P[n] - (float)n * P[n - 1]) * recip[n];
        float e = ex2(aL2 * t2);
        float we    = w * e;
        float wmet2 = -we * t2;
        #pragma unroll
        for (int l = 0; l < 5; l++) {
            g[l]  = fmaf(we,    P[2 * l], g[l]);
            gp[l] = fmaf(wmet2, P[2 * l], gp[l]);
        }
    }

    #pragma unroll
    for (int off = 16; off >= 1; off >>= 1) {
        #pragma unroll
        for (int l = 0; l < 5; l++) {
            g[l]  += __shfl_xor_sync(0xffffffffu, g[l],  off);
            gp[l] += __shfl_xor_sync(0xffffffffu, gp[l], off);
        }
    }

    if (lane == 0) {
        float* o = &g_Gtab[wid * TABW];
        #pragma unroll
        for (int l = 0; l < 5; l++) { o[l] = g[l]; o[5 + l] = gp[l]; }
        o[10] = 0.f; o[11] = 0.f;
    }
}

// ---------------------------------------------------------------------------
// Hermite interpolation of all 5 G_l at alpha, reading g_Gtab via __ldg
// (table is L1-resident; 6 x LDG.128 per eval).
// ---------------------------------------------------------------------------
__device__ __forceinline__ void hermite5g(float a, float* __restrict__ out) {
    float u = (a - AMIN) * INVH;
    u = fminf(fmaxf(u, 0.0f), (float)(NODES - 1) - 1e-4f);
    int j = (int)u;
    float f  = u - (float)j;
    float f2 = f * f;
    float fm = f - 1.0f;
    float h01 = f2 * (3.0f - 2.0f * f);
    float h00 = 1.0f - h01;
    float h10 = (f * fm * fm) * HSTEP;
    float h11 = (f2 * fm) * HSTEP;
    const float4* p = (const float4*)(g_Gtab + j * TABW);
    float4 a0 = __ldg(p + 0), a1 = __ldg(p + 1), a2 = __ldg(p + 2);
    float4 b0 = __ldg(p + 3), b1 = __ldg(p + 4), b2 = __ldg(p + 5);
    float G0[5] = {a0.x, a0.y, a0.z, a0.w, a1.x};
    float P0[5] = {a1.y, a1.z, a1.w, a2.x, a2.y};
    float G1[5] = {b0.x, b0.y, b0.z, b0.w, b1.x};
    float P1[5] = {b1.y, b1.z, b1.w, b2.x, b2.y};
    #pragma unroll
    for (int l = 0; l < 5; l++)
        out[l] = fmaf(h00, G0[l], fmaf(h01, G1[l],
                 fmaf(h10, P0[l], h11 * P1[l])));
}

// compile-time li
#define LI(k) ((((k) >= 1) ? 1 : 0) + (((k) >= 6) ? 1 : 0) + (((k) >= 15) ? 1 : 0) + (((k) >= 28) ? 1 : 0))

// ---------------------------------------------------------------------------
// Mega kernel: block of 16 n's. Phase 0: SH (tid<48) || rho (tid 48..191).
// Phase A: ev-row expansion (tid<144) || S half-rows (tid 144..239) — all
// compile-time-unrolled, no per-element index math. Phase B: linear float4
// copies to global.
// smem (floats): odf_s 2160 | ev_s 6480 | S_s 2160 | rho_s 720 | w_s 48
// ---------------------------------------------------------------------------
__global__ void __launch_bounds__(TPB)
mega_kernel(const float* __restrict__ dirs,
            const float* __restrict__ weights,
            const float4* __restrict__ shapes,
            float* __restrict__ S,
            float* __restrict__ odf,
            float* __restrict__ ev,
            int N) {
    extern __shared__ float sm[];
    float* odf_s = sm;                         // 2160
    float* ev_s  = odf_s + NTUP * KCOLS;       // 6480
    float* S_s   = ev_s + NBLK * BDIM * FDIM * KCOLS;  // 2160
    float* rho_s = S_s + NBLK * BDIM * KCOLS;  // 720
    float* w_s   = rho_s + NTUP * NL * BDIM;   // 48

    int tid = threadIdx.x;
    int n0  = blockIdx.x * NBLK;
    int nloc = N - n0; if (nloc > NBLK) nloc = NBLK;
    int ntup = nloc * FDIM;

    // ---- Phase 0a: SH basis (tid < ntup) ----
    if (tid < ntup) {
        int tuple = n0 * FDIM + tid;
        w_s[tid] = __ldg(&weights[tuple]);

        float x = dirs[tuple * 3 + 0];
        float y = dirs[tuple * 3 + 1];
        float z = dirs[tuple * 3 + 2];
        float inv = rsqrtf(x * x + y * y + z * z);
        x *= inv; y *= inv; z *= inv;

        float s2 = fminf(fmaxf(1.0f - z * z, 0.0f), 1.0f);
        float s = sqrtf(s2);

        float rxy = sqrtf(x * x + y * y);
        bool  havexy = rxy > 0.0f;
        float invr = havexy ? (1.0f / rxy) : 0.0f;
        float cphi = havexy ? x * invr : 1.0f;
        float sphi = y * invr;

        float* val = &odf_s[tid * KCOLS];
        const int base[5] = {0, 1, 6, 15, 28};

#define SH_EMIT(L, M, Pv)                                                    \
        {                                                                    \
            int bi = base[(L) >> 1];                                        \
            float cf = g_coef[bi + (L) + (M)];                              \
            if ((M) == 0) {                                                 \
                val[bi + (L)] = cf * (Pv);                                  \
            } else {                                                        \
                val[bi + (L) + (M)] = cf * (Pv) * cm;                       \
                val[bi + (L) - (M)] = cf * (Pv) * sm_;                      \
            }                                                                \
        }

        float pmm = 1.0f;
        float cm = 1.0f, sm_ = 0.0f;
        #pragma unroll
        for (int m = 0; m <= 8; m++) {
            float p_prev = pmm;
            if ((m & 1) == 0) SH_EMIT(m, m, p_prev);
            if (m < 8) {
                float p_cur = (2.0f * m + 1.0f) * z * p_prev;
                if (((m + 1) & 1) == 0) SH_EMIT(m + 1, m, p_cur);
                #pragma unroll
                for (int l = m + 2; l <= 8; l++) {
                    float p_next = ((2.0f * l - 1.0f) * z * p_cur -
                                    (float)(l + m - 1) * p_prev) / (float)(l - m);
                    p_prev = p_cur; p_cur = p_next;
                    if ((l & 1) == 0) SH_EMIT(l, m, p_cur);
                }
            }
            pmm = -(2.0f * m + 1.0f) * s * pmm;
            float cn = cm * cphi - sm_ * sphi;
            float sn = sm_ * cphi + cm * sphi;
            cm = cn; sm_ = sn;
        }
#undef SH_EMIT
    }

    // ---- Phase 0b: rho, one thread per (tuple, b) (tid in [NTUP, NTUP+ntup*3)) ----
    if (tid >= NTUP && tid < NTUP + ntup * BDIM) {
        int idx = tid - NTUP;
        int tu  = idx / BDIM;
        int b   = idx - tu * BDIM;
        float bv = (float)(b + 1);

        float4 sp = __ldg(&shapes[n0 * FDIM + tu]);   // {D_a, D_epar, D_eperp, z}
        float z = sp.w, omz = 1.0f - z;
        const float LOG2E = 1.4426950408889634f;
        float ebp = ex2(-bv * sp.z * LOG2E);          // e^{-b*Deperp}

        float Ga[5], Gc[5];
        hermite5g(bv * sp.x, Ga);
        hermite5g(bv * (sp.y - sp.z), Gc);
        float c2 = omz * ebp;
        float* o = &rho_s[tu * (NL * BDIM) + b * NL];
        #pragma unroll
        for (int l = 0; l < 5; l++)
            o[l] = fmaf(z, Ga[l], c2 * Gc[l]);
    }
    __syncthreads();   // odf_s, rho_s, w_s ready

    // ---- Phase A1: ev-row expansion, one thread per (nl,b,f) row ----
    if (tid < nloc * BDIM * FDIM) {
        int r   = tid;                   // nl*9 + b*3 + f
        int nl  = r / (BDIM * FDIM);
        int rem = r - nl * (BDIM * FDIM);
        int b   = rem / FDIM;
        int f   = rem - b * FDIM;
        const float* rr = &rho_s[(nl * FDIM + f) * (NL * BDIM) + b * NL];
        float r0 = rr[0], r1 = rr[1], r2 = rr[2], r3 = rr[3], r4 = rr[4];
        float* dst = &ev_s[r * KCOLS];
        #pragma unroll
        for (int k = 0; k < KCOLS; k++) {
            const int li = LI(k);
            dst[k] = (li == 0) ? r0 : (li == 1) ? r1 : (li == 2) ? r2
                   : (li == 3) ? r3 : r4;
        }
    }

    // ---- Phase A2: S half-rows, threads [144, 144 + nloc*3*2) ----
    if (tid >= NBLK * BDIM * FDIM && tid < NBLK * BDIM * FDIM + nloc * BDIM * 2) {
        int idx  = tid - NBLK * BDIM * FDIM;
        int row  = idx >> 1;              // nl*3 + b
        int half = idx & 1;
        int nl   = row / BDIM;
        int b    = row - nl * BDIM;
        int tu0  = nl * FDIM;
        float w0 = w_s[tu0 + 0], w1 = w_s[tu0 + 1], w2 = w_s[tu0 + 2];
        float ra[5], rb[5], rc[5];
        #pragma unroll
        for (int l = 0; l < 5; l++) {
            ra[l] = w0 * rho_s[(tu0 + 0) * (NL * BDIM) + b * NL + l];
            rb[l] = w1 * rho_s[(tu0 + 1) * (NL * BDIM) + b * NL + l];
            rc[l] = w2 * rho_s[(tu0 + 2) * (NL * BDIM) + b * NL + l];
        }
        const float* o0 = &odf_s[(tu0 + 0) * KCOLS];
        const float* o1 = &odf_s[(tu0 + 1) * KCOLS];
        const float* o2 = &odf_s[(tu0 + 2) * KCOLS];
        float* dst = &S_s[row * KCOLS];
        if (half == 0) {
            #pragma unroll
            for (int k = 0; k < 23; k++) {
                const int li = LI(k);
                dst[k] = fmaf(ra[li], o0[k], fmaf(rb[li], o1[k], rc[li] * o2[k]));
            }
        } else {
            #pragma unroll
            for (int k = 23; k < KCOLS; k++) {
                const int li = LI(k);
                dst[k] = fmaf(ra[li], o0[k], fmaf(rb[li], o1[k], rc[li] * o2[k]));
            }
        }
    }
    __syncthreads();   // ev_s, S_s ready

    // ---- Phase B: linear float4 copies to global ----
    {
        int total = ntup * KCOLS;                       // odf: 2160 full
        int nv = total >> 2;
        float* gbase = odf + (size_t)n0 * FDIM * KCOLS;
        float4* dst = (float4*)gbase;
        const float4* src = (const float4*)odf_s;
        for (int i = tid; i < nv; i += TPB) dst[i] = src[i];
        for (int i = (nv << 2) + tid; i < total; i += TPB) gbase[i] = odf_s[i];
    }
    {
        int total = nloc * BDIM * FDIM * KCOLS;         // ev: 6480 full
        int nv = total >> 2;
        float* gbase = ev + (size_t)n0 * BDIM * FDIM * KCOLS;
        float4* dst = (float4*)gbase;
        const float4* src = (const float4*)ev_s;
        for (int i = tid; i < nv; i += TPB) dst[i] = src[i];
        for (int i = (nv << 2) + tid; i < total; i += TPB) gbase[i] = ev_s[i];
    }
    {
        int total = nloc * BDIM * KCOLS;                // S: 2160 full
        int nv = total >> 2;
        float* gbase = S + (size_t)n0 * BDIM * KCOLS;
        float4* dst = (float4*)gbase;
        const float4* src = (const float4*)S_s;
        for (int i = tid; i < nv; i += TPB) dst[i] = src[i];
        for (int i = (nv << 2) + tid; i < total; i += TPB) gbase[i] = S_s[i];
    }
}

// ---------------------------------------------------------------------------
extern "C" void kernel_launch(void* const* d_in, const int* in_sizes, int n_in,
                              void* d_out, int out_size) {
    const float* directs = (const float*)d_in[0];  // (N, F, 3)
    const float* weights = (const float*)d_in[1];  // (N, F)
    const float* shapes  = (const float*)d_in[2];  // (N, F, 4)
    const int*   num_t   = (const int*)d_in[3];    // scalar

    int N = in_sizes[0] / (FDIM * 3);
    if (N > NMAX) N = NMAX;

    float* out = (float*)d_out;
    float* S   = out;                                   // (N, B, 45)
    float* odf = out + (size_t)N * BDIM * KCOLS;        // (N, F, 45)
    float* ev  = odf + (size_t)N * FDIM * KCOLS;        // (N, B, F, 45)

    gtab_kernel<<<(NODES * 32 + 255) / 256, 256>>>(num_t);

    const int smem_bytes = (NTUP * KCOLS + NBLK * BDIM * FDIM * KCOLS +
                            NBLK * BDIM * KCOLS + NTUP * NL * BDIM + NTUP) * 4;
    cudaFuncSetAttribute(mega_kernel, cudaFuncAttributeMaxDynamicSharedMemorySize, smem_bytes);

    int nblocks = (N + NBLK - 1) / NBLK;
    mega_kernel<<<nblocks, TPB, smem_bytes>>>(directs, weights,
                                              (const float4*)shapes,
                                              S, odf, ev, N);
}

// round 9
// speedup vs baseline: 3.8399x; 1.0842x over previous
#include <cuda_runtime.h>
#include <cuda_bf16.h>

#define KCOLS 45
#define NL 5
#define NMAX 8192
#define FDIM 3
#define BDIM 3

// G-table over alpha: G_l(a) = sum_t w_t P_l(t) e^{-a t^2}, plus dG/da.
#define NODES 256
#define AMIN  (-3.25f)
#define AMAX  (3.25f)
#define HSTEP ((AMAX - AMIN) / (float)(NODES - 1))
#define INVH  ((float)(NODES - 1) / (AMAX - AMIN))
#define TABW  12

#define NBLK   16                    // n's per mega-block
#define NTUP   (NBLK * FDIM)         // 48 tuples per block
#define TPB    256                   // threads per block

__device__ float g_coef[KCOLS];
__device__ float g_Gtab[NODES * TABW];

__device__ __forceinline__ float ex2(float x) {
    float r;
    asm("ex2.approx.f32 %0, %1;" : "=f"(r) : "f"(x));
    return r;
}

// ---------------------------------------------------------------------------
// Build G table: TWO warps per alpha node (strided halves, smem combine).
// SH coefs in parallel on block 0 (45 threads).
// ---------------------------------------------------------------------------
__global__ void gtab_kernel(const int* __restrict__ num_t_ptr) {
    __shared__ float part[8][10];
    int tid  = threadIdx.x;
    int node = blockIdx.x * 4 + (tid >> 6);     // 64 threads per node
    int wb   = tid >> 5;                        // warp in block (0..7)
    int sub  = wb & 1;                          // which half of the node pair
    int lane = tid & 31;

    if (blockIdx.x == 0 && tid < KCOLS) {
        int col = tid;
        int l, base;
        if      (col >= 28) { l = 8; base = 28; }
        else if (col >= 15) { l = 6; base = 15; }
        else if (col >= 6)  { l = 4; base = 6;  }
        else if (col >= 1)  { l = 2; base = 1;  }
        else                { l = 0; base = 0;  }
        int m  = col - base - l;
        int ma = m < 0 ? -m : m;
        double r = 1.0;
        for (int q = l - ma + 1; q <= l + ma; q++) r *= (double)q;
        double nrm = sqrt((2.0 * l + 1.0) / (4.0 * 3.14159265358979323846) / r);
        double c = (ma == 0) ? nrm : nrm * 1.4142135623730951;
        g_coef[col] = (float)c;
    }

    const float LOG2E = 1.4426950408889634f;
    float alpha = AMIN + (float)node * HSTEP;
    float aL2 = -alpha * LOG2E;

    int num_t = *num_t_ptr;
    float inv_nm1 = (num_t > 1) ? 1.0f / (float)(num_t - 1) : 0.0f;
    float wbase = 1.0f / (float)num_t;

    const float recip[8] = {1.f, 0.5f, 1.f/3.f, 0.25f, 0.2f, 1.f/6.f, 1.f/7.f, 0.125f};

    float g[5]  = {0.f, 0.f, 0.f, 0.f, 0.f};
    float gp[5] = {0.f, 0.f, 0.f, 0.f, 0.f};

    for (int i = lane + 32 * sub; i < num_t; i += 64) {
        float t = (float)i * inv_nm1;
        float w = (i == 0 || i == num_t - 1) ? 0.5f * wbase : wbase;
        float t2 = t * t;
        float P[9];
        P[0] = 1.0f; P[1] = t;
        #pragma unroll
        for (int n = 1; n < 8; n++)
            P[n + 1] = ((2.0f * n + 1.0f) * t * P[n] - (float)n * P[n - 1]) * recip[n];
        float e = ex2(aL2 * t2);
        float we    = w * e;
        float wmet2 = -we * t2;
        #pragma unroll
        for (int l = 0; l < 5; l++) {
            g[l]  = fmaf(we,    P[2 * l], g[l]);
            gp[l] = fmaf(wmet2, P[2 * l], gp[l]);
        }
    }

    #pragma unroll
    for (int off = 16; off >= 1; off >>= 1) {
        #pragma unroll
        for (int l = 0; l < 5; l++) {
            g[l]  += __shfl_xor_sync(0xffffffffu, g[l],  off);
            gp[l] += __shfl_xor_sync(0xffffffffu, gp[l], off);
        }
    }

    if (lane == 0) {
        #pragma unroll
        for (int l = 0; l < 5; l++) { part[wb][l] = g[l]; part[wb][5 + l] = gp[l]; }
    }
    __syncthreads();

    if (sub == 0 && lane == 0) {
        float* o = &g_Gtab[node * TABW];
        #pragma unroll
        for (int j = 0; j < 10; j++) o[j] = part[wb][j] + part[wb + 1][j];
        o[10] = 0.f; o[11] = 0.f;
    }
}

// ---------------------------------------------------------------------------
// Hermite interpolation of all 5 G_l at alpha, reading g_Gtab via __ldg.
// ---------------------------------------------------------------------------
__device__ __forceinline__ void hermite5g(float a, float* __restrict__ out) {
    float u = (a - AMIN) * INVH;
    u = fminf(fmaxf(u, 0.0f), (float)(NODES - 1) - 1e-4f);
    int j = (int)u;
    float f  = u - (float)j;
    float f2 = f * f;
    float fm = f - 1.0f;
    float h01 = f2 * (3.0f - 2.0f * f);
    float h00 = 1.0f - h01;
    float h10 = (f * fm * fm) * HSTEP;
    float h11 = (f2 * fm) * HSTEP;
    const float4* p = (const float4*)(g_Gtab + j * TABW);
    float4 a0 = __ldg(p + 0), a1 = __ldg(p + 1), a2 = __ldg(p + 2);
    float4 b0 = __ldg(p + 3), b1 = __ldg(p + 4), b2 = __ldg(p + 5);
    float G0[5] = {a0.x, a0.y, a0.z, a0.w, a1.x};
    float P0[5] = {a1.y, a1.z, a1.w, a2.x, a2.y};
    float G1[5] = {b0.x, b0.y, b0.z, b0.w, b1.x};
    float P1[5] = {b1.y, b1.z, b1.w, b2.x, b2.y};
    #pragma unroll
    for (int l = 0; l < 5; l++)
        out[l] = fmaf(h00, G0[l], fmaf(h01, G1[l],
                 fmaf(h10, P0[l], h11 * P1[l])));
}

#define LI(k) ((((k) >= 1) ? 1 : 0) + (((k) >= 6) ? 1 : 0) + (((k) >= 15) ? 1 : 0) + (((k) >= 28) ? 1 : 0))

// ---------------------------------------------------------------------------
// Mega kernel. smem (floats): odf_s 2160 | S_s 2160 | rho_s 720 | w_s 48 |
// li_s 48 ints  => ~20.6 KB  (5 blocks/SM, reg-limited)
// ---------------------------------------------------------------------------
__global__ void __launch_bounds__(TPB)
mega_kernel(const float* __restrict__ dirs,
            const float* __restrict__ weights,
            const float4* __restrict__ shapes,
            float* __restrict__ S,
            float* __restrict__ odf,
            float* __restrict__ ev,
            int N) {
    extern __shared__ float sm[];
    float* odf_s = sm;                               // 2160
    float* S_s   = odf_s + NTUP * KCOLS;             // 2160
    float* rho_s = S_s + NBLK * BDIM * KCOLS;        // 720
    float* w_s   = rho_s + NTUP * NL * BDIM;         // 48
    int*   li_s  = (int*)(w_s + NTUP);               // 48 ints

    int tid = threadIdx.x;
    int n0  = blockIdx.x * NBLK;
    int nloc = N - n0; if (nloc > NBLK) nloc = NBLK;
    int ntup = nloc * FDIM;

    if (tid < KCOLS)
        li_s[tid] = (tid >= 1) + (tid >= 6) + (tid >= 15) + (tid >= 28);

    // ---- Phase 0a: SH basis (tid < ntup); recurrence divides replaced by
    //      compile-time reciprocal multiplies (loop fully unrolled). ----
    if (tid < ntup) {
        int tuple = n0 * FDIM + tid;
        w_s[tid] = __ldg(&weights[tuple]);

        float x = dirs[tuple * 3 + 0];
        float y = dirs[tuple * 3 + 1];
        float z = dirs[tuple * 3 + 2];
        float inv = rsqrtf(x * x + y * y + z * z);
        x *= inv; y *= inv; z *= inv;

        float s2 = fminf(fmaxf(1.0f - z * z, 0.0f), 1.0f);
        float s = sqrtf(s2);

        float rxy = sqrtf(x * x + y * y);
        bool  havexy = rxy > 0.0f;
        float invr = havexy ? (1.0f / rxy) : 0.0f;
        float cphi = havexy ? x * invr : 1.0f;
        float sphi = y * invr;

        float* val = &odf_s[tid * KCOLS];
        const int base[5] = {0, 1, 6, 15, 28};

#define SH_EMIT(L, M, Pv)                                                    \
        {                                                                    \
            int bi = base[(L) >> 1];                                        \
            float cf = g_coef[bi + (L) + (M)];                              \
            if ((M) == 0) {                                                 \
                val[bi + (L)] = cf * (Pv);                                  \
            } else {                                                        \
                val[bi + (L) + (M)] = cf * (Pv) * cm;                       \
                val[bi + (L) - (M)] = cf * (Pv) * sm_;                      \
            }                                                                \
        }

        float pmm = 1.0f;
        float cm = 1.0f, sm_ = 0.0f;
        #pragma unroll
        for (int m = 0; m <= 8; m++) {
            float p_prev = pmm;
            if ((m & 1) == 0) SH_EMIT(m, m, p_prev);
            if (m < 8) {
                float p_cur = (2.0f * m + 1.0f) * z * p_prev;
                if (((m + 1) & 1) == 0) SH_EMIT(m + 1, m, p_cur);
                #pragma unroll
                for (int l = m + 2; l <= 8; l++) {
                    float p_next = ((2.0f * l - 1.0f) * z * p_cur -
                                    (float)(l + m - 1) * p_prev)
                                   * (1.0f / (float)(l - m));
                    p_prev = p_cur; p_cur = p_next;
                    if ((l & 1) == 0) SH_EMIT(l, m, p_cur);
                }
            }
            pmm = -(2.0f * m + 1.0f) * s * pmm;
            float cn = cm * cphi - sm_ * sphi;
            float sn = sm_ * cphi + cm * sphi;
            cm = cn; sm_ = sn;
        }
#undef SH_EMIT
    }

    // ---- Phase 0b: rho, one thread per (tuple, b) ----
    if (tid >= NTUP && tid < NTUP + ntup * BDIM) {
        int idx = tid - NTUP;
        int tu  = idx / BDIM;
        int b   = idx - tu * BDIM;
        float bv = (float)(b + 1);

        float4 sp = __ldg(&shapes[n0 * FDIM + tu]);
        float z = sp.w, omz = 1.0f - z;
        const float LOG2E = 1.4426950408889634f;
        float ebp = ex2(-bv * sp.z * LOG2E);

        float Ga[5], Gc[5];
        hermite5g(bv * sp.x, Ga);
        hermite5g(bv * (sp.y - sp.z), Gc);
        float c2 = omz * ebp;
        float* o = &rho_s[tu * (NL * BDIM) + b * NL];
        #pragma unroll
        for (int l = 0; l < 5; l++)
            o[l] = fmaf(z, Ga[l], c2 * Gc[l]);
    }
    __syncthreads();   // odf_s, rho_s, w_s, li_s ready

    // ---- Phase A: S half-rows on tid<96 (into S_s) ----
    if (tid < nloc * BDIM * 2) {
        int row  = tid >> 1;              // nl*3 + b
        int half = tid & 1;
        int nl   = row / BDIM;
        int b    = row - nl * BDIM;
        int tu0  = nl * FDIM;
        float w0 = w_s[tu0 + 0], w1 = w_s[tu0 + 1], w2 = w_s[tu0 + 2];
        float ra[5], rb[5], rc[5];
        #pragma unroll
        for (int l = 0; l < 5; l++) {
            ra[l] = w0 * rho_s[(tu0 + 0) * (NL * BDIM) + b * NL + l];
            rb[l] = w1 * rho_s[(tu0 + 1) * (NL * BDIM) + b * NL + l];
            rc[l] = w2 * rho_s[(tu0 + 2) * (NL * BDIM) + b * NL + l];
        }
        const float* o0 = &odf_s[(tu0 + 0) * KCOLS];
        const float* o1 = &odf_s[(tu0 + 1) * KCOLS];
        const float* o2 = &odf_s[(tu0 + 2) * KCOLS];
        float* dst = &S_s[row * KCOLS];
        if (half == 0) {
            #pragma unroll
            for (int k = 0; k < 23; k++) {
                const int li = LI(k);
                dst[k] = fmaf(ra[li], o0[k], fmaf(rb[li], o1[k], rc[li] * o2[k]));
            }
        } else {
            #pragma unroll
            for (int k = 23; k < KCOLS; k++) {
                const int li = LI(k);
                dst[k] = fmaf(ra[li], o0[k], fmaf(rb[li], o1[k], rc[li] * o2[k]));
            }
        }
    }

    // ---- Phase A (all threads): emit ev DIRECTLY from rho_s (float4) ----
    {
        int total = nloc * BDIM * FDIM * KCOLS;   // 6480 full
        int nv = total >> 2;
        float* gbase = ev + (size_t)n0 * BDIM * FDIM * KCOLS;
        float4* dst4 = (float4*)gbase;
        for (int i = tid; i < nv; i += TPB) {
            int e = i << 2;
            int row = e / KCOLS;                  // nl*9 + b*3 + f
            int k   = e - row * KCOLS;
            int nl  = row / (BDIM * FDIM);
            int rm  = row - nl * (BDIM * FDIM);
            int b   = rm / FDIM;
            int f   = rm - b * FDIM;
            const float* rr = &rho_s[(nl * FDIM + f) * (NL * BDIM) + b * NL];
            float v[4];
            #pragma unroll
            for (int j = 0; j < 4; j++) {
                v[j] = rr[li_s[k]];
                if (++k == KCOLS) {
                    k = 0;
                    if (++f == FDIM) { f = 0; if (++b == BDIM) { b = 0; nl++; } }
                    rr = &rho_s[(nl * FDIM + f) * (NL * BDIM) + b * NL];
                }
            }
            dst4[i] = make_float4(v[0], v[1], v[2], v[3]);
        }
        for (int e = (nv << 2) + tid; e < total; e += TPB) {
            int row = e / KCOLS;
            int k   = e - row * KCOLS;
            int nl  = row / (BDIM * FDIM);
            int rm  = row - nl * (BDIM * FDIM);
            int b   = rm / FDIM;
            int f   = rm - b * FDIM;
            gbase[e] = rho_s[(nl * FDIM + f) * (NL * BDIM) + b * NL + li_s[k]];
        }
    }

    // ---- emit odf (float4 linear copy) ----
    {
        int total = ntup * KCOLS;                 // 2160 full
        int nv = total >> 2;
        float* gbase = odf + (size_t)n0 * FDIM * KCOLS;
        float4* dst = (float4*)gbase;
        const float4* src = (const float4*)odf_s;
        for (int i = tid; i < nv; i += TPB) dst[i] = src[i];
        for (int i = (nv << 2) + tid; i < total; i += TPB) gbase[i] = odf_s[i];
    }
    __syncthreads();   // S_s ready

    // ---- emit S (float4 linear copy) ----
    {
        int total = nloc * BDIM * KCOLS;          // 2160 full
        int nv = total >> 2;
        float* gbase = S + (size_t)n0 * BDIM * KCOLS;
        float4* dst = (float4*)gbase;
        const float4* src = (const float4*)S_s;
        for (int i = tid; i < nv; i += TPB) dst[i] = src[i];
        for (int i = (nv << 2) + tid; i < total; i += TPB) gbase[i] = S_s[i];
    }
}

// ---------------------------------------------------------------------------
extern "C" void kernel_launch(void* const* d_in, const int* in_sizes, int n_in,
                              void* d_out, int out_size) {
    const float* directs = (const float*)d_in[0];  // (N, F, 3)
    const float* weights = (const float*)d_in[1];  // (N, F)
    const float* shapes  = (const float*)d_in[2];  // (N, F, 4)
    const int*   num_t   = (const int*)d_in[3];    // scalar

    int N = in_sizes[0] / (FDIM * 3);
    if (N > NMAX) N = NMAX;

    float* out = (float*)d_out;
    float* S   = out;                                   // (N, B, 45)
    float* odf = out + (size_t)N * BDIM * KCOLS;        // (N, F, 45)
    float* ev  = odf + (size_t)N * FDIM * KCOLS;        // (N, B, F, 45)

    gtab_kernel<<<NODES / 4, 256>>>(num_t);

    const int smem_bytes = (NTUP * KCOLS + NBLK * BDIM * KCOLS +
                            NTUP * NL * BDIM + NTUP + KCOLS + 3) * 4;
    cudaFuncSetAttribute(mega_kernel, cudaFuncAttributeMaxDynamicSharedMemorySize, smem_bytes);

    int nblocks = (N + NBLK - 1) / NBLK;
    mega_kernel<<<nblocks, TPB, smem_bytes>>>(directs, weights,
                                              (const float4*)shapes,
                                              S, odf, ev, N);
}

// round 10
// speedup vs baseline: 4.3495x; 1.1327x over previous
#include <cuda_runtime.h>
#include <cuda_bf16.h>

#define KCOLS 45
#define NL 5
#define NMAX 8192
#define FDIM 3
#define BDIM 3

// G-table over alpha: G_l(a) = sum_t w_t P_l(t) e^{-a t^2}, plus dG/da.
#define NODES 256
#define AMIN  (-3.25f)
#define AMAX  (3.25f)
#define HSTEP ((AMAX - AMIN) / (float)(NODES - 1))
#define INVH  ((float)(NODES - 1) / (AMAX - AMIN))
#define TABW  12

#define NBLK   8                     // n's per mega-block
#define NTUP   (NBLK * FDIM)         // 24 tuples per block
#define TPB    128                   // threads per block

__device__ float g_Gtab[NODES * TABW];

__device__ __forceinline__ float ex2(float x) {
    float r;
    asm("ex2.approx.f32 %0, %1;" : "=f"(r) : "f"(x));
    return r;
}

// ---------------------------------------------------------------------------
// Build G table: TWO warps per alpha node (strided halves, smem combine).
// ---------------------------------------------------------------------------
__global__ void gtab_kernel(const int* __restrict__ num_t_ptr) {
    __shared__ float part[8][10];
    int tid  = threadIdx.x;
    int node = blockIdx.x * 4 + (tid >> 6);     // 64 threads per node
    int wb   = tid >> 5;
    int sub  = wb & 1;
    int lane = tid & 31;

    const float LOG2E = 1.4426950408889634f;
    float alpha = AMIN + (float)node * HSTEP;
    float aL2 = -alpha * LOG2E;

    int num_t = *num_t_ptr;
    float inv_nm1 = (num_t > 1) ? 1.0f / (float)(num_t - 1) : 0.0f;
    float wbase = 1.0f / (float)num_t;

    const float recip[8] = {1.f, 0.5f, 1.f/3.f, 0.25f, 0.2f, 1.f/6.f, 1.f/7.f, 0.125f};

    float g[5]  = {0.f, 0.f, 0.f, 0.f, 0.f};
    float gp[5] = {0.f, 0.f, 0.f, 0.f, 0.f};

    for (int i = lane + 32 * sub; i < num_t; i += 64) {
        float t = (float)i * inv_nm1;
        float w = (i == 0 || i == num_t - 1) ? 0.5f * wbase : wbase;
        float t2 = t * t;
        float P[9];
        P[0] = 1.0f; P[1] = t;
        #pragma unroll
        for (int n = 1; n < 8; n++)
            P[n + 1] = ((2.0f * n + 1.0f) * t * P[n] - (float)n * P[n - 1]) * recip[n];
        float e = ex2(aL2 * t2);
        float we    = w * e;
        float wmet2 = -we * t2;
        #pragma unroll
        for (int l = 0; l < 5; l++) {
            g[l]  = fmaf(we,    P[2 * l], g[l]);
            gp[l] = fmaf(wmet2, P[2 * l], gp[l]);
        }
    }

    #pragma unroll
    for (int off = 16; off >= 1; off >>= 1) {
        #pragma unroll
        for (int l = 0; l < 5; l++) {
            g[l]  += __shfl_xor_sync(0xffffffffu, g[l],  off);
            gp[l] += __shfl_xor_sync(0xffffffffu, gp[l], off);
        }
    }

    if (lane == 0) {
        #pragma unroll
        for (int l = 0; l < 5; l++) { part[wb][l] = g[l]; part[wb][5 + l] = gp[l]; }
    }
    __syncthreads();

    if (sub == 0 && lane == 0) {
        float* o = &g_Gtab[node * TABW];
        #pragma unroll
        for (int j = 0; j < 10; j++) o[j] = part[wb][j] + part[wb + 1][j];
        o[10] = 0.f; o[11] = 0.f;
    }
}

// ---------------------------------------------------------------------------
// Hermite interpolation of all 5 G_l at alpha, reading g_Gtab via __ldg.
// ---------------------------------------------------------------------------
__device__ __forceinline__ void hermite5g(float a, float* __restrict__ out) {
    float u = (a - AMIN) * INVH;
    u = fminf(fmaxf(u, 0.0f), (float)(NODES - 1) - 1e-4f);
    int j = (int)u;
    float f  = u - (float)j;
    float f2 = f * f;
    float fm = f - 1.0f;
    float h01 = f2 * (3.0f - 2.0f * f);
    float h00 = 1.0f - h01;
    float h10 = (f * fm * fm) * HSTEP;
    float h11 = (f2 * fm) * HSTEP;
    const float4* p = (const float4*)(g_Gtab + j * TABW);
    float4 a0 = __ldg(p + 0), a1 = __ldg(p + 1), a2 = __ldg(p + 2);
    float4 b0 = __ldg(p + 3), b1 = __ldg(p + 4), b2 = __ldg(p + 5);
    float G0[5] = {a0.x, a0.y, a0.z, a0.w, a1.x};
    float P0[5] = {a1.y, a1.z, a1.w, a2.x, a2.y};
    float G1[5] = {b0.x, b0.y, b0.z, b0.w, b1.x};
    float P1[5] = {b1.y, b1.z, b1.w, b2.x, b2.y};
    #pragma unroll
    for (int l = 0; l < 5; l++)
        out[l] = fmaf(h00, G0[l], fmaf(h01, G1[l],
                 fmaf(h10, P0[l], h11 * P1[l])));
}

#define LI(k) ((((k) >= 1) ? 1 : 0) + (((k) >= 6) ? 1 : 0) + (((k) >= 15) ? 1 : 0) + (((k) >= 28) ? 1 : 0))

// ---------------------------------------------------------------------------
// Mega kernel (PDL secondary). Block of 8 n's (24 tuples), 128 threads.
// Coefs computed per-block in fp32 — no dependency on gtab for the SH phase;
// only rho threads gridDepSync on gtab's table.
// smem (floats): coef 45(+3 pad) | odf_s 1080 | S_s 1080 | rho_s 360 | w_s 24 | li_s 48i
// ---------------------------------------------------------------------------
__global__ void __launch_bounds__(TPB)
mega_kernel(const float* __restrict__ dirs,
            const float* __restrict__ weights,
            const float4* __restrict__ shapes,
            float* __restrict__ S,
            float* __restrict__ odf,
            float* __restrict__ ev,
            int N) {
    extern __shared__ float sm[];
    float* coef_s = sm;                                // 48 (45 used)
    float* odf_s  = coef_s + 48;                       // 1080
    float* S_s    = odf_s + NTUP * KCOLS;              // 1080
    float* rho_s  = S_s + NBLK * BDIM * KCOLS;         // 360
    float* w_s    = rho_s + NTUP * NL * BDIM;          // 24
    int*   li_s   = (int*)(w_s + NTUP);                // 48 ints

    int tid = threadIdx.x;
    int n0  = blockIdx.x * NBLK;
    int nloc = N - n0; if (nloc > NBLK) nloc = NBLK;
    int ntup = nloc * FDIM;

    // ---- Phase -1: per-block SH coefs (fp32) + li table ----
    if (tid < KCOLS) {
        int col = tid;
        int l, base;
        if      (col >= 28) { l = 8; base = 28; }
        else if (col >= 15) { l = 6; base = 15; }
        else if (col >= 6)  { l = 4; base = 6;  }
        else if (col >= 1)  { l = 2; base = 1;  }
        else                { l = 0; base = 0;  }
        int m  = col - base - l;
        int ma = m < 0 ? -m : m;
        float r = 1.0f;
        for (int q = l - ma + 1; q <= l + ma; q++) r *= (float)q;
        float nrm = sqrtf((2.0f * l + 1.0f) * 0.07957747154594767f / r);
        coef_s[col] = (ma == 0) ? nrm : nrm * 1.4142135623730951f;
    }
    if (tid >= 64 && tid < 64 + KCOLS) {
        int k = tid - 64;
        li_s[k] = (k >= 1) + (k >= 6) + (k >= 15) + (k >= 28);
    }
    if (tid < ntup)
        w_s[tid] = __ldg(&weights[n0 * FDIM + tid]);
    __syncthreads();   // coef_s, li_s, w_s

    // ---- Phase 0a: SH basis (tid < ntup), fully independent of gtab ----
    if (tid < ntup) {
        int tuple = n0 * FDIM + tid;

        float x = dirs[tuple * 3 + 0];
        float y = dirs[tuple * 3 + 1];
        float z = dirs[tuple * 3 + 2];
        float inv = rsqrtf(x * x + y * y + z * z);
        x *= inv; y *= inv; z *= inv;

        float s2 = fminf(fmaxf(1.0f - z * z, 0.0f), 1.0f);
        float s = sqrtf(s2);

        float rxy = sqrtf(x * x + y * y);
        bool  havexy = rxy > 0.0f;
        float invr = havexy ? (1.0f / rxy) : 0.0f;
        float cphi = havexy ? x * invr : 1.0f;
        float sphi = y * invr;

        float* val = &odf_s[tid * KCOLS];
        const int base[5] = {0, 1, 6, 15, 28};

#define SH_EMIT(L, M, Pv)                                                    \
        {                                                                    \
            int bi = base[(L) >> 1];                                        \
            float cf = coef_s[bi + (L) + (M)];                              \
            if ((M) == 0) {                                                 \
                val[bi + (L)] = cf * (Pv);                                  \
            } else {                                                        \
                val[bi + (L) + (M)] = cf * (Pv) * cm;                       \
                val[bi + (L) - (M)] = cf * (Pv) * sm_;                      \
            }                                                                \
        }

        float pmm = 1.0f;
        float cm = 1.0f, sm_ = 0.0f;
        #pragma unroll
        for (int m = 0; m <= 8; m++) {
            float p_prev = pmm;
            if ((m & 1) == 0) SH_EMIT(m, m, p_prev);
            if (m < 8) {
                float p_cur = (2.0f * m + 1.0f) * z * p_prev;
                if (((m + 1) & 1) == 0) SH_EMIT(m + 1, m, p_cur);
                #pragma unroll
                for (int l = m + 2; l <= 8; l++) {
                    float p_next = ((2.0f * l - 1.0f) * z * p_cur -
                                    (float)(l + m - 1) * p_prev)
                                   * (1.0f / (float)(l - m));
                    p_prev = p_cur; p_cur = p_next;
                    if ((l & 1) == 0) SH_EMIT(l, m, p_cur);
                }
            }
            pmm = -(2.0f * m + 1.0f) * s * pmm;
            float cn = cm * cphi - sm_ * sphi;
            float sn = sm_ * cphi + cm * sphi;
            cm = cn; sm_ = sn;
        }
#undef SH_EMIT
    }

    // ---- Phase 0b: rho, one thread per (tuple, b); waits on gtab via PDL ----
    if (tid >= NTUP && tid < NTUP + ntup * BDIM) {
        cudaGridDependencySynchronize();   // g_Gtab ready

        int idx = tid - NTUP;
        int tu  = idx / BDIM;
        int b   = idx - tu * BDIM;
        float bv = (float)(b + 1);

        float4 sp = __ldg(&shapes[n0 * FDIM + tu]);
        float z = sp.w, omz = 1.0f - z;
        const float LOG2E = 1.4426950408889634f;
        float ebp = ex2(-bv * sp.z * LOG2E);

        float Ga[5], Gc[5];
        hermite5g(bv * sp.x, Ga);
        hermite5g(bv * (sp.y - sp.z), Gc);
        float c2 = omz * ebp;
        float* o = &rho_s[tu * (NL * BDIM) + b * NL];
        #pragma unroll
        for (int l = 0; l < 5; l++)
            o[l] = fmaf(z, Ga[l], c2 * Gc[l]);
    }
    __syncthreads();   // odf_s, rho_s ready

    // ---- Phase A: S half-rows on tid < nloc*6 (into S_s) ----
    if (tid < nloc * BDIM * 2) {
        int row  = tid >> 1;              // nl*3 + b
        int half = tid & 1;
        int nl   = row / BDIM;
        int b    = row - nl * BDIM;
        int tu0  = nl * FDIM;
        float w0 = w_s[tu0 + 0], w1 = w_s[tu0 + 1], w2 = w_s[tu0 + 2];
        float ra[5], rb[5], rc[5];
        #pragma unroll
        for (int l = 0; l < 5; l++) {
            ra[l] = w0 * rho_s[(tu0 + 0) * (NL * BDIM) + b * NL + l];
            rb[l] = w1 * rho_s[(tu0 + 1) * (NL * BDIM) + b * NL + l];
            rc[l] = w2 * rho_s[(tu0 + 2) * (NL * BDIM) + b * NL + l];
        }
        const float* o0 = &odf_s[(tu0 + 0) * KCOLS];
        const float* o1 = &odf_s[(tu0 + 1) * KCOLS];
        const float* o2 = &odf_s[(tu0 + 2) * KCOLS];
        float* dst = &S_s[row * KCOLS];
        if (half == 0) {
            #pragma unroll
            for (int k = 0; k < 23; k++) {
                const int li = LI(k);
                dst[k] = fmaf(ra[li], o0[k], fmaf(rb[li], o1[k], rc[li] * o2[k]));
            }
        } else {
            #pragma unroll
            for (int k = 23; k < KCOLS; k++) {
                const int li = LI(k);
                dst[k] = fmaf(ra[li], o0[k], fmaf(rb[li], o1[k], rc[li] * o2[k]));
            }
        }
    }

    // ---- emit ev directly from rho_s (float4) ----
    {
        int total = nloc * BDIM * FDIM * KCOLS;   // 3240 full
        int nv = total >> 2;
        float* gbase = ev + (size_t)n0 * BDIM * FDIM * KCOLS;
        float4* dst4 = (float4*)gbase;
        for (int i = tid; i < nv; i += TPB) {
            int e = i << 2;
            int row = e / KCOLS;                  // nl*9 + b*3 + f
            int k   = e - row * KCOLS;
            int nl  = row / (BDIM * FDIM);
            int rm  = row - nl * (BDIM * FDIM);
            int b   = rm / FDIM;
            int f   = rm - b * FDIM;
            const float* rr = &rho_s[(nl * FDIM + f) * (NL * BDIM) + b * NL];
            float v[4];
            #pragma unroll
            for (int j = 0; j < 4; j++) {
                v[j] = rr[li_s[k]];
                if (++k == KCOLS) {
                    k = 0;
                    if (++f == FDIM) { f = 0; if (++b == BDIM) { b = 0; nl++; } }
                    rr = &rho_s[(nl * FDIM + f) * (NL * BDIM) + b * NL];
                }
            }
            dst4[i] = make_float4(v[0], v[1], v[2], v[3]);
        }
        for (int e = (nv << 2) + tid; e < total; e += TPB) {
            int row = e / KCOLS;
            int k   = e - row * KCOLS;
            int nl  = row / (BDIM * FDIM);
            int rm  = row - nl * (BDIM * FDIM);
            int b   = rm / FDIM;
            int f   = rm - b * FDIM;
            gbase[e] = rho_s[(nl * FDIM + f) * (NL * BDIM) + b * NL + li_s[k]];
        }
    }

    // ---- emit odf (float4 linear copy) ----
    {
        int total = ntup * KCOLS;                 // 1080 full
        int nv = total >> 2;
        float* gbase = odf + (size_t)n0 * FDIM * KCOLS;
        float4* dst = (float4*)gbase;
        const float4* src = (const float4*)odf_s;
        for (int i = tid; i < nv; i += TPB) dst[i] = src[i];
        for (int i = (nv << 2) + tid; i < total; i += TPB) gbase[i] = odf_s[i];
    }
    __syncthreads();   // S_s ready

    // ---- emit S (float4 linear copy) ----
    {
        int total = nloc * BDIM * KCOLS;          // 1080 full
        int nv = total >> 2;
        float* gbase = S + (size_t)n0 * BDIM * KCOLS;
        float4* dst = (float4*)gbase;
        const float4* src = (const float4*)S_s;
        for (int i = tid; i < nv; i += TPB) dst[i] = src[i];
        for (int i = (nv << 2) + tid; i < total; i += TPB) gbase[i] = S_s[i];
    }
}

// ---------------------------------------------------------------------------
extern "C" void kernel_launch(void* const* d_in, const int* in_sizes, int n_in,
                              void* d_out, int out_size) {
    const float* directs = (const float*)d_in[0];  // (N, F, 3)
    const float* weights = (const float*)d_in[1];  // (N, F)
    const float* shapes  = (const float*)d_in[2];  // (N, F, 4)
    const int*   num_t   = (const int*)d_in[3];    // scalar

    int N = in_sizes[0] / (FDIM * 3);
    if (N > NMAX) N = NMAX;

    float* out = (float*)d_out;
    float* S   = out;                                   // (N, B, 45)
    float* odf = out + (size_t)N * BDIM * KCOLS;        // (N, F, 45)
    float* ev  = odf + (size_t)N * FDIM * KCOLS;        // (N, B, F, 45)

    gtab_kernel<<<NODES / 4, 256>>>(num_t);

    const int smem_bytes = (48 + NTUP * KCOLS + NBLK * BDIM * KCOLS +
                            NTUP * NL * BDIM + NTUP + 48) * 4;
    int nblocks = (N + NBLK - 1) / NBLK;

    // PDL launch: mega may start while gtab runs; rho threads gridDepSync.
    cudaLaunchConfig_t cfg = {};
    cfg.gridDim = dim3((unsigned)nblocks, 1, 1);
    cfg.blockDim = dim3(TPB, 1, 1);
    cfg.dynamicSmemBytes = (size_t)smem_bytes;
    cfg.stream = 0;
    cudaLaunchAttribute attr[1];
    attr[0].id = cudaLaunchAttributeProgrammaticStreamSerialization;
    attr[0].val.programmaticStreamSerializationAllowed = 1;
    cfg.attrs = attr;
    cfg.numAttrs = 1;
    cudaLaunchKernelEx(&cfg, mega_kernel, directs, weights,
                       (const float4*)shapes, S, odf, ev, N);
}

// round 11
// speedup vs baseline: 4.4072x; 1.0133x over previous
#include <cuda_runtime.h>
#include <cuda_bf16.h>

#define KCOLS 45
#define NL 5
#define NMAX 8192
#define FDIM 3
#define BDIM 3

// G-table over alpha: G_l(a) = sum_t w_t P_l(t) e^{-a t^2}, plus dG/da.
#define NODES 256
#define AMIN  (-3.25f)
#define AMAX  (3.25f)
#define HSTEP ((AMAX - AMIN) / (float)(NODES - 1))
#define INVH  ((float)(NODES - 1) / (AMAX - AMIN))
#define TABW  12

#define NBLK   8                     // n's per mega-block
#define NTUP   (NBLK * FDIM)         // 24 tuples per block
#define TPB    256                   // threads per block

__device__ float g_Gtab[NODES * TABW];

__device__ __forceinline__ float ex2(float x) {
    float r;
    asm("ex2.approx.f32 %0, %1;" : "=f"(r) : "f"(x));
    return r;
}

// ---------------------------------------------------------------------------
// Build G table: TWO warps per alpha node (strided halves, smem combine).
// ---------------------------------------------------------------------------
__global__ void gtab_kernel(const int* __restrict__ num_t_ptr) {
    __shared__ float part[8][10];
    int tid  = threadIdx.x;
    int node = blockIdx.x * 4 + (tid >> 6);     // 64 threads per node
    int wb   = tid >> 5;
    int sub  = wb & 1;
    int lane = tid & 31;

    const float LOG2E = 1.4426950408889634f;
    float alpha = AMIN + (float)node * HSTEP;
    float aL2 = -alpha * LOG2E;

    int num_t = *num_t_ptr;
    float inv_nm1 = (num_t > 1) ? 1.0f / (float)(num_t - 1) : 0.0f;
    float wbase = 1.0f / (float)num_t;

    const float recip[8] = {1.f, 0.5f, 1.f/3.f, 0.25f, 0.2f, 1.f/6.f, 1.f/7.f, 0.125f};

    float g[5]  = {0.f, 0.f, 0.f, 0.f, 0.f};
    float gp[5] = {0.f, 0.f, 0.f, 0.f, 0.f};

    for (int i = lane + 32 * sub; i < num_t; i += 64) {
        float t = (float)i * inv_nm1;
        float w = (i == 0 || i == num_t - 1) ? 0.5f * wbase : wbase;
        float t2 = t * t;
        float P[9];
        P[0] = 1.0f; P[1] = t;
        #pragma unroll
        for (int n = 1; n < 8; n++)
            P[n + 1] = ((2.0f * n + 1.0f) * t * P[n] - (float)n * P[n - 1]) * recip[n];
        float e = ex2(aL2 * t2);
        float we    = w * e;
        float wmet2 = -we * t2;
        #pragma unroll
        for (int l = 0; l < 5; l++) {
            g[l]  = fmaf(we,    P[2 * l], g[l]);
            gp[l] = fmaf(wmet2, P[2 * l], gp[l]);
        }
    }

    #pragma unroll
    for (int off = 16; off >= 1; off >>= 1) {
        #pragma unroll
        for (int l = 0; l < 5; l++) {
            g[l]  += __shfl_xor_sync(0xffffffffu, g[l],  off);
            gp[l] += __shfl_xor_sync(0xffffffffu, gp[l], off);
        }
    }

    if (lane == 0) {
        #pragma unroll
        for (int l = 0; l < 5; l++) { part[wb][l] = g[l]; part[wb][5 + l] = gp[l]; }
    }
    __syncthreads();

    if (sub == 0 && lane == 0) {
        float* o = &g_Gtab[node * TABW];
        #pragma unroll
        for (int j = 0; j < 10; j++) o[j] = part[wb][j] + part[wb + 1][j];
        o[10] = 0.f; o[11] = 0.f;
    }
}

// ---------------------------------------------------------------------------
// Hermite interpolation of all 5 G_l at alpha, reading g_Gtab via __ldg.
// ---------------------------------------------------------------------------
__device__ __forceinline__ void hermite5g(float a, float* __restrict__ out) {
    float u = (a - AMIN) * INVH;
    u = fminf(fmaxf(u, 0.0f), (float)(NODES - 1) - 1e-4f);
    int j = (int)u;
    float f  = u - (float)j;
    float f2 = f * f;
    float fm = f - 1.0f;
    float h01 = f2 * (3.0f - 2.0f * f);
    float h00 = 1.0f - h01;
    float h10 = (f * fm * fm) * HSTEP;
    float h11 = (f2 * fm) * HSTEP;
    const float4* p = (const float4*)(g_Gtab + j * TABW);
    float4 a0 = __ldg(p + 0), a1 = __ldg(p + 1), a2 = __ldg(p + 2);
    float4 b0 = __ldg(p + 3), b1 = __ldg(p + 4), b2 = __ldg(p + 5);
    float G0[5] = {a0.x, a0.y, a0.z, a0.w, a1.x};
    float P0[5] = {a1.y, a1.z, a1.w, a2.x, a2.y};
    float G1[5] = {b0.x, b0.y, b0.z, b0.w, b1.x};
    float P1[5] = {b1.y, b1.z, b1.w, b2.x, b2.y};
    #pragma unroll
    for (int l = 0; l < 5; l++)
        out[l] = fmaf(h00, G0[l], fmaf(h01, G1[l],
                 fmaf(h10, P0[l], h11 * P1[l])));
}

#define LI(k) ((((k) >= 1) ? 1 : 0) + (((k) >= 6) ? 1 : 0) + (((k) >= 15) ? 1 : 0) + (((k) >= 28) ? 1 : 0))

// ---------------------------------------------------------------------------
// Mega kernel (PDL secondary). Block of 8 n's (24 tuples), 256 threads.
// rho_s laid out (nl, b, f, l) — ev's row order — so the ev emit needs only
// one /45 per float4.
// smem (floats): coef 48 | odf_s 1080 | S_s 1080 | rho_s 360 | w_s 24 | li_s 48i
// ---------------------------------------------------------------------------
__global__ void __launch_bounds__(TPB, 6)
mega_kernel(const float* __restrict__ dirs,
            const float* __restrict__ weights,
            const float4* __restrict__ shapes,
            float* __restrict__ S,
            float* __restrict__ odf,
            float* __restrict__ ev,
            int N) {
    extern __shared__ float sm[];
    float* coef_s = sm;                                // 48 (45 used)
    float* odf_s  = coef_s + 48;                       // 1080
    float* S_s    = odf_s + NTUP * KCOLS;              // 1080
    float* rho_s  = S_s + NBLK * BDIM * KCOLS;         // 360, layout (nl,b,f,l)
    float* w_s    = rho_s + NTUP * NL * BDIM;          // 24
    int*   li_s   = (int*)(w_s + NTUP);                // 48 ints

    int tid = threadIdx.x;
    int n0  = blockIdx.x * NBLK;
    int nloc = N - n0; if (nloc > NBLK) nloc = NBLK;
    int ntup = nloc * FDIM;

    // ---- Phase -1: per-block SH coefs (fp32) + li table + weights ----
    if (tid < KCOLS) {
        int col = tid;
        int l, base;
        if      (col >= 28) { l = 8; base = 28; }
        else if (col >= 15) { l = 6; base = 15; }
        else if (col >= 6)  { l = 4; base = 6;  }
        else if (col >= 1)  { l = 2; base = 1;  }
        else                { l = 0; base = 0;  }
        int m  = col - base - l;
        int ma = m < 0 ? -m : m;
        float r = 1.0f;
        for (int q = l - ma + 1; q <= l + ma; q++) r *= (float)q;
        float nrm = sqrtf((2.0f * l + 1.0f) * 0.07957747154594767f / r);
        coef_s[col] = (ma == 0) ? nrm : nrm * 1.4142135623730951f;
    }
    if (tid >= 64 && tid < 64 + KCOLS) {
        int k = tid - 64;
        li_s[k] = (k >= 1) + (k >= 6) + (k >= 15) + (k >= 28);
    }
    if (tid >= 128 && tid < 128 + ntup)
        w_s[tid - 128] = __ldg(&weights[n0 * FDIM + tid - 128]);
    __syncthreads();   // coef_s, li_s, w_s

    // ---- Phase 0a: SH basis (tid < ntup), independent of gtab ----
    if (tid < ntup) {
        int tuple = n0 * FDIM + tid;

        float x = dirs[tuple * 3 + 0];
        float y = dirs[tuple * 3 + 1];
        float z = dirs[tuple * 3 + 2];
        float inv = rsqrtf(x * x + y * y + z * z);
        x *= inv; y *= inv; z *= inv;

        float s2 = fminf(fmaxf(1.0f - z * z, 0.0f), 1.0f);
        float s = sqrtf(s2);

        float rxy = sqrtf(x * x + y * y);
        bool  havexy = rxy > 0.0f;
        float invr = havexy ? (1.0f / rxy) : 0.0f;
        float cphi = havexy ? x * invr : 1.0f;
        float sphi = y * invr;

        float* val = &odf_s[tid * KCOLS];
        const int base[5] = {0, 1, 6, 15, 28};

#define SH_EMIT(L, M, Pv)                                                    \
        {                                                                    \
            int bi = base[(L) >> 1];                                        \
            float cf = coef_s[bi + (L) + (M)];                              \
            if ((M) == 0) {                                                 \
                val[bi + (L)] = cf * (Pv);                                  \
            } else {                                                        \
                val[bi + (L) + (M)] = cf * (Pv) * cm;                       \
                val[bi + (L) - (M)] = cf * (Pv) * sm_;                      \
            }                                                                \
        }

        float pmm = 1.0f;
        float cm = 1.0f, sm_ = 0.0f;
        #pragma unroll
        for (int m = 0; m <= 8; m++) {
            float p_prev = pmm;
            if ((m & 1) == 0) SH_EMIT(m, m, p_prev);
            if (m < 8) {
                float p_cur = (2.0f * m + 1.0f) * z * p_prev;
                if (((m + 1) & 1) == 0) SH_EMIT(m + 1, m, p_cur);
                #pragma unroll
                for (int l = m + 2; l <= 8; l++) {
                    float p_next = ((2.0f * l - 1.0f) * z * p_cur -
                                    (float)(l + m - 1) * p_prev)
                                   * (1.0f / (float)(l - m));
                    p_prev = p_cur; p_cur = p_next;
                    if ((l & 1) == 0) SH_EMIT(l, m, p_cur);
                }
            }
            pmm = -(2.0f * m + 1.0f) * s * pmm;
            float cn = cm * cphi - sm_ * sphi;
            float sn = sm_ * cphi + cm * sphi;
            cm = cn; sm_ = sn;
        }
#undef SH_EMIT
    }

    // ---- Phase 0b: rho, one thread per (tuple, b), warps 1-3; PDL wait ----
    if (tid >= 32 && tid < 32 + ntup * BDIM) {
        cudaGridDependencySynchronize();   // g_Gtab ready

        int idx = tid - 32;
        int tu  = idx / BDIM;
        int b   = idx - tu * BDIM;
        int nl  = tu / FDIM;
        int f   = tu - nl * FDIM;
        float bv = (float)(b + 1);

        float4 sp = __ldg(&shapes[n0 * FDIM + tu]);
        float z = sp.w, omz = 1.0f - z;
        const float LOG2E = 1.4426950408889634f;
        float ebp = ex2(-bv * sp.z * LOG2E);

        float Ga[5], Gc[5];
        hermite5g(bv * sp.x, Ga);
        hermite5g(bv * (sp.y - sp.z), Gc);
        float c2 = omz * ebp;
        float* o = &rho_s[((nl * BDIM + b) * FDIM + f) * NL];
        #pragma unroll
        for (int l = 0; l < 5; l++)
            o[l] = fmaf(z, Ga[l], c2 * Gc[l]);
    }
    __syncthreads();   // odf_s, rho_s ready

    // ---- Phase A: S half-rows on tid < nloc*6 (into S_s) ----
    if (tid < nloc * BDIM * 2) {
        int row  = tid >> 1;              // nl*3 + b
        int half = tid & 1;
        int nl   = row / BDIM;
        int b    = row - nl * BDIM;
        int tu0  = nl * FDIM;
        float w0 = w_s[tu0 + 0], w1 = w_s[tu0 + 1], w2 = w_s[tu0 + 2];
        const float* rbase = &rho_s[(nl * BDIM + b) * FDIM * NL];
        float ra[5], rb[5], rc[5];
        #pragma unroll
        for (int l = 0; l < 5; l++) {
            ra[l] = w0 * rbase[0 * NL + l];
            rb[l] = w1 * rbase[1 * NL + l];
            rc[l] = w2 * rbase[2 * NL + l];
        }
        const float* o0 = &odf_s[(tu0 + 0) * KCOLS];
        const float* o1 = &odf_s[(tu0 + 1) * KCOLS];
        const float* o2 = &odf_s[(tu0 + 2) * KCOLS];
        float* dst = &S_s[row * KCOLS];
        if (half == 0) {
            #pragma unroll
            for (int k = 0; k < 23; k++) {
                const int li = LI(k);
                dst[k] = fmaf(ra[li], o0[k], fmaf(rb[li], o1[k], rc[li] * o2[k]));
            }
        } else {
            #pragma unroll
            for (int k = 23; k < KCOLS; k++) {
                const int li = LI(k);
                dst[k] = fmaf(ra[li], o0[k], fmaf(rb[li], o1[k], rc[li] * o2[k]));
            }
        }
    }

    // ---- emit ev directly from rho_s (float4; rho_s rows == ev rows) ----
    {
        int total = nloc * BDIM * FDIM * KCOLS;   // 3240 full
        int nv = total >> 2;
        float* gbase = ev + (size_t)n0 * BDIM * FDIM * KCOLS;
        float4* dst4 = (float4*)gbase;
        for (int i = tid; i < nv; i += TPB) {
            int e = i << 2;
            int row = e / KCOLS;
            int k   = e - row * KCOLS;
            const float* rr = &rho_s[row * NL];
            float v[4];
            #pragma unroll
            for (int j = 0; j < 4; j++) {
                v[j] = rr[li_s[k]];
                if (++k == KCOLS) { k = 0; rr += NL; }
            }
            dst4[i] = make_float4(v[0], v[1], v[2], v[3]);
        }
        for (int e = (nv << 2) + tid; e < total; e += TPB) {
            int row = e / KCOLS;
            int k   = e - row * KCOLS;
            gbase[e] = rho_s[row * NL + li_s[k]];
        }
    }

    // ---- emit odf (float4 linear copy) ----
    {
        int total = ntup * KCOLS;                 // 1080 full
        int nv = total >> 2;
        float* gbase = odf + (size_t)n0 * FDIM * KCOLS;
        float4* dst = (float4*)gbase;
        const float4* src = (const float4*)odf_s;
        for (int i = tid; i < nv; i += TPB) dst[i] = src[i];
        for (int i = (nv << 2) + tid; i < total; i += TPB) gbase[i] = odf_s[i];
    }
    __syncthreads();   // S_s ready

    // ---- emit S (float4 linear copy) ----
    {
        int total = nloc * BDIM * KCOLS;          // 1080 full
        int nv = total >> 2;
        float* gbase = S + (size_t)n0 * BDIM * KCOLS;
        float4* dst = (float4*)gbase;
        const float4* src = (const float4*)S_s;
        for (int i = tid; i < nv; i += TPB) dst[i] = src[i];
        for (int i = (nv << 2) + tid; i < total; i += TPB) gbase[i] = S_s[i];
    }
}

// ---------------------------------------------------------------------------
extern "C" void kernel_launch(void* const* d_in, const int* in_sizes, int n_in,
                              void* d_out, int out_size) {
    const float* directs = (const float*)d_in[0];  // (N, F, 3)
    const float* weights = (const float*)d_in[1];  // (N, F)
    const float* shapes  = (const float*)d_in[2];  // (N, F, 4)
    const int*   num_t   = (const int*)d_in[3];    // scalar

    int N = in_sizes[0] / (FDIM * 3);
    if (N > NMAX) N = NMAX;

    float* out = (float*)d_out;
    float* S   = out;                                   // (N, B, 45)
    float* odf = out + (size_t)N * BDIM * KCOLS;        // (N, F, 45)
    float* ev  = odf + (size_t)N * FDIM * KCOLS;        // (N, B, F, 45)

    gtab_kernel<<<NODES / 4, 256>>>(num_t);

    const int smem_bytes = (48 + NTUP * KCOLS + NBLK * BDIM * KCOLS +
                            NTUP * NL * BDIM + NTUP + 48) * 4;
    int nblocks = (N + NBLK - 1) / NBLK;

    // PDL launch: mega may start while gtab runs; rho threads gridDepSync.
    cudaLaunchConfig_t cfg = {};
    cfg.gridDim = dim3((unsigned)nblocks, 1, 1);
    cfg.blockDim = dim3(TPB, 1, 1);
    cfg.dynamicSmemBytes = (size_t)smem_bytes;
    cfg.stream = 0;
    cudaLaunchAttribute attr[1];
    attr[0].id = cudaLaunchAttributeProgrammaticStreamSerialization;
    attr[0].val.programmaticStreamSerializationAllowed = 1;
    cfg.attrs = attr;
    cfg.numAttrs = 1;
    cudaLaunchKernelEx(&cfg, mega_kernel, directs, weights,
                       (const float4*)shapes, S, odf, ev, N);
}

// round 12
// speedup vs baseline: 4.8079x; 1.0909x over previous
#include <cuda_runtime.h>
#include <cuda_bf16.h>

#define KCOLS 45
#define NL 5
#define NMAX 8192
#define FDIM 3
#define BDIM 3

// G-table over alpha: G_l(a) = sum_t w_t P_l(t) e^{-a t^2}, plus dG/da.
#define NODES 256
#define AMIN  (-3.25f)
#define AMAX  (3.25f)
#define HSTEP ((AMAX - AMIN) / (float)(NODES - 1))
#define INVH  ((float)(NODES - 1) / (AMAX - AMIN))
#define TABW  12

#define NBLK   8                     // n's per mega-block
#define NTUP   (NBLK * FDIM)         // 24 tuples per block
#define TPB    256                   // threads per block (8 warps)

__device__ float g_Gtab[NODES * TABW];

__device__ __forceinline__ float ex2(float x) {
    float r;
    asm("ex2.approx.f32 %0, %1;" : "=f"(r) : "f"(x));
    return r;
}

// ---------------------------------------------------------------------------
// Build G table: TWO warps per alpha node (strided halves, smem combine).
// ---------------------------------------------------------------------------
__global__ void gtab_kernel(const int* __restrict__ num_t_ptr) {
    __shared__ float part[8][10];
    int tid  = threadIdx.x;
    int node = blockIdx.x * 4 + (tid >> 6);     // 64 threads per node
    int wb   = tid >> 5;
    int sub  = wb & 1;
    int lane = tid & 31;

    const float LOG2E = 1.4426950408889634f;
    float alpha = AMIN + (float)node * HSTEP;
    float aL2 = -alpha * LOG2E;

    int num_t = *num_t_ptr;
    float inv_nm1 = (num_t > 1) ? 1.0f / (float)(num_t - 1) : 0.0f;
    float wbase = 1.0f / (float)num_t;

    const float recip[8] = {1.f, 0.5f, 1.f/3.f, 0.25f, 0.2f, 1.f/6.f, 1.f/7.f, 0.125f};

    float g[5]  = {0.f, 0.f, 0.f, 0.f, 0.f};
    float gp[5] = {0.f, 0.f, 0.f, 0.f, 0.f};

    for (int i = lane + 32 * sub; i < num_t; i += 64) {
        float t = (float)i * inv_nm1;
        float w = (i == 0 || i == num_t - 1) ? 0.5f * wbase : wbase;
        float t2 = t * t;
        float P[9];
        P[0] = 1.0f; P[1] = t;
        #pragma unroll
        for (int n = 1; n < 8; n++)
            P[n + 1] = ((2.0f * n + 1.0f) * t * P[n] - (float)n * P[n - 1]) * recip[n];
        float e = ex2(aL2 * t2);
        float we    = w * e;
        float wmet2 = -we * t2;
        #pragma unroll
        for (int l = 0; l < 5; l++) {
            g[l]  = fmaf(we,    P[2 * l], g[l]);
            gp[l] = fmaf(wmet2, P[2 * l], gp[l]);
        }
    }

    #pragma unroll
    for (int off = 16; off >= 1; off >>= 1) {
        #pragma unroll
        for (int l = 0; l < 5; l++) {
            g[l]  += __shfl_xor_sync(0xffffffffu, g[l],  off);
            gp[l] += __shfl_xor_sync(0xffffffffu, gp[l], off);
        }
    }

    if (lane == 0) {
        #pragma unroll
        for (int l = 0; l < 5; l++) { part[wb][l] = g[l]; part[wb][5 + l] = gp[l]; }
    }
    __syncthreads();

    if (sub == 0 && lane == 0) {
        float* o = &g_Gtab[node * TABW];
        #pragma unroll
        for (int j = 0; j < 10; j++) o[j] = part[wb][j] + part[wb + 1][j];
        o[10] = 0.f; o[11] = 0.f;
    }
}

// ---------------------------------------------------------------------------
// Hermite interpolation of all 5 G_l at alpha, reading g_Gtab via __ldg.
// ---------------------------------------------------------------------------
__device__ __forceinline__ void hermite5g(float a, float* __restrict__ out) {
    float u = (a - AMIN) * INVH;
    u = fminf(fmaxf(u, 0.0f), (float)(NODES - 1) - 1e-4f);
    int j = (int)u;
    float f  = u - (float)j;
    float f2 = f * f;
    float fm = f - 1.0f;
    float h01 = f2 * (3.0f - 2.0f * f);
    float h00 = 1.0f - h01;
    float h10 = (f * fm * fm) * HSTEP;
    float h11 = (f2 * fm) * HSTEP;
    const float4* p = (const float4*)(g_Gtab + j * TABW);
    float4 a0 = __ldg(p + 0), a1 = __ldg(p + 1), a2 = __ldg(p + 2);
    float4 b0 = __ldg(p + 3), b1 = __ldg(p + 4), b2 = __ldg(p + 5);
    float G0[5] = {a0.x, a0.y, a0.z, a0.w, a1.x};
    float P0[5] = {a1.y, a1.z, a1.w, a2.x, a2.y};
    float G1[5] = {b0.x, b0.y, b0.z, b0.w, b1.x};
    float P1[5] = {b1.y, b1.z, b1.w, b2.x, b2.y};
    #pragma unroll
    for (int l = 0; l < 5; l++)
        out[l] = fmaf(h00, G0[l], fmaf(h01, G1[l],
                 fmaf(h10, P0[l], h11 * P1[l])));
}

// ---------------------------------------------------------------------------
// Mega kernel (PDL secondary). Block of 8 n's (24 tuples), 256 threads.
// rho_s layout (nl, b, f, l) = ev row order.
// Emits are warp-per-row with LANE-CONSTANT k/li: no divergence, no index
// tables, no S staging. smem: coef 48 | odf_s 1080 | rho_s 360 | w_s 24.
// ---------------------------------------------------------------------------
__global__ void __launch_bounds__(TPB, 6)
mega_kernel(const float* __restrict__ dirs,
            const float* __restrict__ weights,
            const float4* __restrict__ shapes,
            float* __restrict__ S,
            float* __restrict__ odf,
            float* __restrict__ ev,
            int N) {
    extern __shared__ float sm[];
    float* coef_s = sm;                                // 48 (45 used)
    float* odf_s  = coef_s + 48;                       // 1080
    float* rho_s  = odf_s + NTUP * KCOLS;              // 360, layout (nl,b,f,l)
    float* w_s    = rho_s + NTUP * NL * BDIM;          // 24

    int tid  = threadIdx.x;
    int wid  = tid >> 5;
    int lane = tid & 31;
    int n0   = blockIdx.x * NBLK;
    int nloc = N - n0; if (nloc > NBLK) nloc = NBLK;
    int ntup = nloc * FDIM;

    // ---- Phase -1: per-block SH coefs (fp32) + weights ----
    if (tid < KCOLS) {
        int col = tid;
        int l, base;
        if      (col >= 28) { l = 8; base = 28; }
        else if (col >= 15) { l = 6; base = 15; }
        else if (col >= 6)  { l = 4; base = 6;  }
        else if (col >= 1)  { l = 2; base = 1;  }
        else                { l = 0; base = 0;  }
        int m  = col - base - l;
        int ma = m < 0 ? -m : m;
        float r = 1.0f;
        for (int q = l - ma + 1; q <= l + ma; q++) r *= (float)q;
        float nrm = sqrtf((2.0f * l + 1.0f) * 0.07957747154594767f / r);
        coef_s[col] = (ma == 0) ? nrm : nrm * 1.4142135623730951f;
    }
    if (tid >= 128 && tid < 128 + ntup)
        w_s[tid - 128] = __ldg(&weights[n0 * FDIM + tid - 128]);
    __syncthreads();   // coef_s, w_s

    // ---- Phase 0a: SH basis (tid < ntup), independent of gtab ----
    if (tid < ntup) {
        int tuple = n0 * FDIM + tid;

        float x = dirs[tuple * 3 + 0];
        float y = dirs[tuple * 3 + 1];
        float z = dirs[tuple * 3 + 2];
        float inv = rsqrtf(x * x + y * y + z * z);
        x *= inv; y *= inv; z *= inv;

        float s2 = fminf(fmaxf(1.0f - z * z, 0.0f), 1.0f);
        float s = sqrtf(s2);

        float rxy = sqrtf(x * x + y * y);
        bool  havexy = rxy > 0.0f;
        float invr = havexy ? (1.0f / rxy) : 0.0f;
        float cphi = havexy ? x * invr : 1.0f;
        float sphi = y * invr;

        float* val = &odf_s[tid * KCOLS];
        const int base[5] = {0, 1, 6, 15, 28};

#define SH_EMIT(L, M, Pv)                                                    \
        {                                                                    \
            int bi = base[(L) >> 1];                                        \
            float cf = coef_s[bi + (L) + (M)];                              \
            if ((M) == 0) {                                                 \
                val[bi + (L)] = cf * (Pv);                                  \
            } else {                                                        \
                val[bi + (L) + (M)] = cf * (Pv) * cm;                       \
                val[bi + (L) - (M)] = cf * (Pv) * sm_;                      \
            }                                                                \
        }

        float pmm = 1.0f;
        float cm = 1.0f, sm_ = 0.0f;
        #pragma unroll
        for (int m = 0; m <= 8; m++) {
            float p_prev = pmm;
            if ((m & 1) == 0) SH_EMIT(m, m, p_prev);
            if (m < 8) {
                float p_cur = (2.0f * m + 1.0f) * z * p_prev;
                if (((m + 1) & 1) == 0) SH_EMIT(m + 1, m, p_cur);
                #pragma unroll
                for (int l = m + 2; l <= 8; l++) {
                    float p_next = ((2.0f * l - 1.0f) * z * p_cur -
                                    (float)(l + m - 1) * p_prev)
                                   * (1.0f / (float)(l - m));
                    p_prev = p_cur; p_cur = p_next;
                    if ((l & 1) == 0) SH_EMIT(l, m, p_cur);
                }
            }
            pmm = -(2.0f * m + 1.0f) * s * pmm;
            float cn = cm * cphi - sm_ * sphi;
            float sn = sm_ * cphi + cm * sphi;
            cm = cn; sm_ = sn;
        }
#undef SH_EMIT
    }

    // ---- Phase 0b: rho, one thread per (tuple, b), warps 1-3; PDL wait ----
    if (tid >= 32 && tid < 32 + ntup * BDIM) {
        cudaGridDependencySynchronize();   // g_Gtab ready

        int idx = tid - 32;
        int tu  = idx / BDIM;
        int b   = idx - tu * BDIM;
        int nl  = tu / FDIM;
        int f   = tu - nl * FDIM;
        float bv = (float)(b + 1);

        float4 sp = __ldg(&shapes[n0 * FDIM + tu]);
        float z = sp.w, omz = 1.0f - z;
        const float LOG2E = 1.4426950408889634f;
        float ebp = ex2(-bv * sp.z * LOG2E);

        float Ga[5], Gc[5];
        hermite5g(bv * sp.x, Ga);
        hermite5g(bv * (sp.y - sp.z), Gc);
        float c2 = omz * ebp;
        float* o = &rho_s[((nl * BDIM + b) * FDIM + f) * NL];
        #pragma unroll
        for (int l = 0; l < 5; l++)
            o[l] = fmaf(z, Ga[l], c2 * Gc[l]);
    }
    __syncthreads();   // odf_s, rho_s ready

    // Lane-constant k / li for the 45-wide row emits.
    int k1 = lane;                 // always < 45
    int k2 = lane + 32;            // valid when lane < 13
    int li1 = (k1 >= 1) + (k1 >= 6) + (k1 >= 15) + (k1 >= 28);
    int li2 = (k2 >= 15) ? ((k2 >= 28) ? 4 : 3) : 2;   // k2 in [32,44] -> 4
    bool has2 = (lane < KCOLS - 32);

    // ---- emit ev: warp-per-row; rho_s rows == ev rows ----
    {
        int nrows = nloc * BDIM * FDIM;            // 72 full
        float* gbase = ev + (size_t)n0 * BDIM * FDIM * KCOLS;
        for (int row = wid; row < nrows; row += 8) {
            const float* rr = &rho_s[row * NL];
            float* g = gbase + row * KCOLS;
            g[k1] = rr[li1];
            if (has2) g[k2] = rr[li2];
        }
    }

    // ---- emit S: warp-per-row, computed directly to global ----
    {
        int nrows = nloc * BDIM;                   // 24 full
        float* gbase = S + (size_t)n0 * BDIM * KCOLS;
        for (int row = wid; row < nrows; row += 8) {
            int nl = row / BDIM;
            int b  = row - nl * BDIM;
            const float* rb = &rho_s[(nl * BDIM + b) * FDIM * NL];
            float w0 = w_s[nl * FDIM + 0];
            float w1 = w_s[nl * FDIM + 1];
            float w2 = w_s[nl * FDIM + 2];
            const float* o0 = &odf_s[(nl * FDIM + 0) * KCOLS];
            const float* o1 = &odf_s[(nl * FDIM + 1) * KCOLS];
            const float* o2 = &odf_s[(nl * FDIM + 2) * KCOLS];
            float* g = gbase + row * KCOLS;
            {
                float acc = w0 * rb[0 * NL + li1] * o0[k1];
                acc = fmaf(w1 * rb[1 * NL + li1], o1[k1], acc);
                acc = fmaf(w2 * rb[2 * NL + li1], o2[k1], acc);
                g[k1] = acc;
            }
            if (has2) {
                float acc = w0 * rb[0 * NL + li2] * o0[k2];
                acc = fmaf(w1 * rb[1 * NL + li2], o1[k2], acc);
                acc = fmaf(w2 * rb[2 * NL + li2], o2[k2], acc);
                g[k2] = acc;
            }
        }
    }

    // ---- emit odf (float4 linear copy) ----
    {
        int total = ntup * KCOLS;                  // 1080 full
        int nv = total >> 2;
        float* gbase = odf + (size_t)n0 * FDIM * KCOLS;
        float4* dst = (float4*)gbase;
        const float4* src = (const float4*)odf_s;
        for (int i = tid; i < nv; i += TPB) dst[i] = src[i];
        for (int i = (nv << 2) + tid; i < total; i += TPB) gbase[i] = odf_s[i];
    }
}

// ---------------------------------------------------------------------------
extern "C" void kernel_launch(void* const* d_in, const int* in_sizes, int n_in,
                              void* d_out, int out_size) {
    const float* directs = (const float*)d_in[0];  // (N, F, 3)
    const float* weights = (const float*)d_in[1];  // (N, F)
    const float* shapes  = (const float*)d_in[2];  // (N, F, 4)
    const int*   num_t   = (const int*)d_in[3];    // scalar

    int N = in_sizes[0] / (FDIM * 3);
    if (N > NMAX) N = NMAX;

    float* out = (float*)d_out;
    float* S   = out;                                   // (N, B, 45)
    float* odf = out + (size_t)N * BDIM * KCOLS;        // (N, F, 45)
    float* ev  = odf + (size_t)N * FDIM * KCOLS;        // (N, B, F, 45)

    gtab_kernel<<<NODES / 4, 256>>>(num_t);

    const int smem_bytes = (48 + NTUP * KCOLS + NTUP * NL * BDIM + NTUP) * 4;
    int nblocks = (N + NBLK - 1) / NBLK;

    // PDL launch: mega may start while gtab runs; rho threads gridDepSync.
    cudaLaunchConfig_t cfg = {};
    cfg.gridDim = dim3((unsigned)nblocks, 1, 1);
    cfg.blockDim = dim3(TPB, 1, 1);
    cfg.dynamicSmemBytes = (size_t)smem_bytes;
    cfg.stream = 0;
    cudaLaunchAttribute attr[1];
    attr[0].id = cudaLaunchAttributeProgrammaticStreamSerialization;
    attr[0].val.programmaticStreamSerializationAllowed = 1;
    cfg.attrs = attr;
    cfg.numAttrs = 1;
    cudaLaunchKernelEx(&cfg, mega_kernel, directs, weights,
                       (const float4*)shapes, S, odf, ev, N);
}

// round 13
// speedup vs baseline: 5.8321x; 1.2130x over previous
#include <cuda_runtime.h>
#include <cuda_bf16.h>

#define KCOLS 45
#define NL 5
#define NMAX 8192
#define FDIM 3
#define BDIM 3

#define NBLK   8                     // n's per mega-block
#define NTUP   (NBLK * FDIM)         // 24 tuples per block
#define TPB    256                   // threads per block (8 warps)

#define NGAUSS 16
#define GSTRIDE 8                    // smem floats per gauss node

// 16-point Gauss-Legendre on [-1,1]: 8 symmetric (x, w) pairs.
__device__ __constant__ float c_gx[8] = {
    0.0950125098376374f, 0.2816035507792589f, 0.4580167776572274f,
    0.6178762444026438f, 0.7554044083550030f, 0.8656312023878318f,
    0.9445750230732326f, 0.9894009349916499f
};
__device__ __constant__ float c_gw[8] = {
    0.1894506104550685f, 0.1826034150449236f, 0.1691565193950025f,
    0.1495959888165767f, 0.1246289712555339f, 0.0951585116824928f,
    0.0622535239386479f, 0.0271524594117541f
};

__device__ __forceinline__ float ex2(float x) {
    float r;
    asm("ex2.approx.f32 %0, %1;" : "=f"(r) : "f"(x));
    return r;
}

// ---------------------------------------------------------------------------
// Single mega kernel. Block of 8 n's (24 tuples), 256 threads.
// rho_l = z*G_l(b*Da) + (1-z)*e^{-b*Deperp}*G_l(b*(Depar-Deperp)), where
// G_l(a) = scale * sum_i gw_i * P_l(t_i) * e^{-a t_i^2}  (16-pt Gauss on [0,1],
// scale = (num_t-1)/num_t matches the reference's 1/num_t trapezoid weights).
// smem (floats): coef 48 | gauss 128 | odf_s 1080 | rho_s 360 | w_s 24
// ---------------------------------------------------------------------------
__global__ void __launch_bounds__(TPB, 6)
mega_kernel(const float* __restrict__ dirs,
            const float* __restrict__ weights,
            const float4* __restrict__ shapes,
            const int* __restrict__ num_t_ptr,
            float* __restrict__ S,
            float* __restrict__ odf,
            float* __restrict__ ev,
            int N) {
    extern __shared__ float sm[];
    float* coef_s  = sm;                               // 48 (45 used)
    float* gauss_s = coef_s + 48;                      // 16*8 = 128
    float* odf_s   = gauss_s + NGAUSS * GSTRIDE;       // 1080
    float* rho_s   = odf_s + NTUP * KCOLS;             // 360, layout (nl,b,f,l)
    float* w_s     = rho_s + NTUP * NL * BDIM;         // 24

    int tid  = threadIdx.x;
    int wid  = tid >> 5;
    int lane = tid & 31;
    int n0   = blockIdx.x * NBLK;
    int nloc = N - n0; if (nloc > NBLK) nloc = NBLK;
    int ntup = nloc * FDIM;

    // ---- Phase -1a: SH normalization coefs (fp32, 45 threads) ----
    if (tid < KCOLS) {
        int col = tid;
        int l, base;
        if      (col >= 28) { l = 8; base = 28; }
        else if (col >= 15) { l = 6; base = 15; }
        else if (col >= 6)  { l = 4; base = 6;  }
        else if (col >= 1)  { l = 2; base = 1;  }
        else                { l = 0; base = 0;  }
        int m  = col - base - l;
        int ma = m < 0 ? -m : m;
        float r = 1.0f;
        for (int q = l - ma + 1; q <= l + ma; q++) r *= (float)q;
        float nrm = sqrtf((2.0f * l + 1.0f) * 0.07957747154594767f / r);
        coef_s[col] = (ma == 0) ? nrm : nrm * 1.4142135623730951f;
    }

    // ---- Phase -1b: Gauss node table (16 threads: 64..79) ----
    if (tid >= 64 && tid < 64 + NGAUSS) {
        int j = tid - 64;
        int p = j >> 1;
        float sgn = (j & 1) ? 1.0f : -1.0f;
        float t = fmaf(0.5f * sgn, c_gx[p], 0.5f);       // node on [0,1]
        int num_t = *num_t_ptr;
        float scale = (num_t > 0) ? (float)(num_t - 1) / (float)num_t : 1.0f;
        float gw = 0.5f * c_gw[p] * scale;
        const float recip[8] = {1.f, 0.5f, 1.f/3.f, 0.25f, 0.2f, 1.f/6.f, 1.f/7.f, 0.125f};
        float P[9];
        P[0] = 1.0f; P[1] = t;
        #pragma unroll
        for (int n = 1; n < 8; n++)
            P[n + 1] = ((2.0f * n + 1.0f) * t * P[n] - (float)n * P[n - 1]) * recip[n];
        float* g = &gauss_s[j * GSTRIDE];
        g[0] = t * t;
        #pragma unroll
        for (int l = 0; l < 5; l++) g[1 + l] = gw * P[2 * l];
        g[6] = 0.f; g[7] = 0.f;
    }

    // ---- Phase -1c: weights (threads 128..) ----
    if (tid >= 128 && tid < 128 + ntup)
        w_s[tid - 128] = __ldg(&weights[n0 * FDIM + tid - 128]);
    __syncthreads();   // coef_s, gauss_s, w_s

    // ---- Phase 0a: SH basis (tid < ntup) ----
    if (tid < ntup) {
        int tuple = n0 * FDIM + tid;

        float x = dirs[tuple * 3 + 0];
        float y = dirs[tuple * 3 + 1];
        float z = dirs[tuple * 3 + 2];
        float inv = rsqrtf(x * x + y * y + z * z);
        x *= inv; y *= inv; z *= inv;

        float s2 = fminf(fmaxf(1.0f - z * z, 0.0f), 1.0f);
        float s = sqrtf(s2);

        float rxy = sqrtf(x * x + y * y);
        bool  havexy = rxy > 0.0f;
        float invr = havexy ? (1.0f / rxy) : 0.0f;
        float cphi = havexy ? x * invr : 1.0f;
        float sphi = y * invr;

        float* val = &odf_s[tid * KCOLS];
        const int base[5] = {0, 1, 6, 15, 28};

#define SH_EMIT(L, M, Pv)                                                    \
        {                                                                    \
            int bi = base[(L) >> 1];                                        \
            float cf = coef_s[bi + (L) + (M)];                              \
            if ((M) == 0) {                                                 \
                val[bi + (L)] = cf * (Pv);                                  \
            } else {                                                        \
                val[bi + (L) + (M)] = cf * (Pv) * cm;                       \
                val[bi + (L) - (M)] = cf * (Pv) * sm_;                      \
            }                                                                \
        }

        float pmm = 1.0f;
        float cm = 1.0f, sm_ = 0.0f;
        #pragma unroll
        for (int m = 0; m <= 8; m++) {
            float p_prev = pmm;
            if ((m & 1) == 0) SH_EMIT(m, m, p_prev);
            if (m < 8) {
                float p_cur = (2.0f * m + 1.0f) * z * p_prev;
                if (((m + 1) & 1) == 0) SH_EMIT(m + 1, m, p_cur);
                #pragma unroll
                for (int l = m + 2; l <= 8; l++) {
                    float p_next = ((2.0f * l - 1.0f) * z * p_cur -
                                    (float)(l + m - 1) * p_prev)
                                   * (1.0f / (float)(l - m));
                    p_prev = p_cur; p_cur = p_next;
                    if ((l & 1) == 0) SH_EMIT(l, m, p_cur);
                }
            }
            pmm = -(2.0f * m + 1.0f) * s * pmm;
            float cn = cm * cphi - sm_ * sphi;
            float sn = sm_ * cphi + cm * sphi;
            cm = cn; sm_ = sn;
        }
#undef SH_EMIT
    }

    // ---- Phase 0b: rho via inline Gauss quadrature, one thread per (tuple,b) ----
    if (tid >= 32 && tid < 32 + ntup * BDIM) {
        int idx = tid - 32;
        int tu  = idx / BDIM;
        int b   = idx - tu * BDIM;
        int nl  = tu / FDIM;
        int f   = tu - nl * FDIM;
        float bv = (float)(b + 1);

        float4 sp = __ldg(&shapes[n0 * FDIM + tu]);   // {D_a, D_epar, D_eperp, z}
        float z = sp.w, omz = 1.0f - z;
        const float LOG2E = 1.4426950408889634f;
        float a1 = -bv * sp.x * LOG2E;                 // exp2 coef for b*Da
        float a2 = -bv * (sp.y - sp.z) * LOG2E;        // exp2 coef for b*dd
        float c2 = omz * ex2(-bv * sp.z * LOG2E);      // (1-z) e^{-b*Deperp}

        float acc[5] = {0.f, 0.f, 0.f, 0.f, 0.f};
        #pragma unroll
        for (int j = 0; j < NGAUSS; j++) {
            const float4* g4 = (const float4*)&gauss_s[j * GSTRIDE];
            float4 ga = g4[0];            // {t2, wP0, wP2, wP4}
            float4 gb = g4[1];            // {wP6, wP8, 0, 0}
            float t2 = ga.x;
            float e1 = ex2(a1 * t2);
            float e2 = ex2(a2 * t2);
            float kj = fmaf(z, e1, c2 * e2);
            acc[0] = fmaf(kj, ga.y, acc[0]);
            acc[1] = fmaf(kj, ga.z, acc[1]);
            acc[2] = fmaf(kj, ga.w, acc[2]);
            acc[3] = fmaf(kj, gb.x, acc[3]);
            acc[4] = fmaf(kj, gb.y, acc[4]);
        }

        float* o = &rho_s[((nl * BDIM + b) * FDIM + f) * NL];
        #pragma unroll
        for (int l = 0; l < 5; l++) o[l] = acc[l];
    }
    __syncthreads();   // odf_s, rho_s ready

    // Lane-constant k / li for the 45-wide row emits.
    int k1 = lane;                 // always < 45
    int k2 = lane + 32;            // valid when lane < 13
    int li1 = (k1 >= 1) + (k1 >= 6) + (k1 >= 15) + (k1 >= 28);
    int li2 = (k2 >= 15) ? ((k2 >= 28) ? 4 : 3) : 2;
    bool has2 = (lane < KCOLS - 32);

    // ---- emit ev: warp-per-row; rho_s rows == ev rows ----
    {
        int nrows = nloc * BDIM * FDIM;            // 72 full
        float* gbase = ev + (size_t)n0 * BDIM * FDIM * KCOLS;
        for (int row = wid; row < nrows; row += 8) {
            const float* rr = &rho_s[row * NL];
            float* g = gbase + row * KCOLS;
            g[k1] = rr[li1];
            if (has2) g[k2] = rr[li2];
        }
    }

    // ---- emit S: warp-per-row, computed directly to global ----
    {
        int nrows = nloc * BDIM;                   // 24 full
        float* gbase = S + (size_t)n0 * BDIM * KCOLS;
        for (int row = wid; row < nrows; row += 8) {
            int nl = row / BDIM;
            int b  = row - nl * BDIM;
            const float* rb = &rho_s[(nl * BDIM + b) * FDIM * NL];
            float w0 = w_s[nl * FDIM + 0];
            float w1 = w_s[nl * FDIM + 1];
            float w2 = w_s[nl * FDIM + 2];
            const float* o0 = &odf_s[(nl * FDIM + 0) * KCOLS];
            const float* o1 = &odf_s[(nl * FDIM + 1) * KCOLS];
            const float* o2 = &odf_s[(nl * FDIM + 2) * KCOLS];
            float* g = gbase + row * KCOLS;
            {
                float acc = w0 * rb[0 * NL + li1] * o0[k1];
                acc = fmaf(w1 * rb[1 * NL + li1], o1[k1], acc);
                acc = fmaf(w2 * rb[2 * NL + li1], o2[k1], acc);
                g[k1] = acc;
            }
            if (has2) {
                float acc = w0 * rb[0 * NL + li2] * o0[k2];
                acc = fmaf(w1 * rb[1 * NL + li2], o1[k2], acc);
                acc = fmaf(w2 * rb[2 * NL + li2], o2[k2], acc);
                g[k2] = acc;
            }
        }
    }

    // ---- emit odf (float4 linear copy) ----
    {
        int total = ntup * KCOLS;                  // 1080 full
        int nv = total >> 2;
        float* gbase = odf + (size_t)n0 * FDIM * KCOLS;
        float4* dst = (float4*)gbase;
        const float4* src = (const float4*)odf_s;
        for (int i = tid; i < nv; i += TPB) dst[i] = src[i];
        for (int i = (nv << 2) + tid; i < total; i += TPB) gbase[i] = odf_s[i];
    }
}

// ---------------------------------------------------------------------------
extern "C" void kernel_launch(void* const* d_in, const int* in_sizes, int n_in,
                              void* d_out, int out_size) {
    const float* directs = (const float*)d_in[0];  // (N, F, 3)
    const float* weights = (const float*)d_in[1];  // (N, F)
    const float* shapes  = (const float*)d_in[2];  // (N, F, 4)
    const int*   num_t   = (const int*)d_in[3];    // scalar

    int N = in_sizes[0] / (FDIM * 3);
    if (N > NMAX) N = NMAX;

    float* out = (float*)d_out;
    float* S   = out;                                   // (N, B, 45)
    float* odf = out + (size_t)N * BDIM * KCOLS;        // (N, F, 45)
    float* ev  = odf + (size_t)N * FDIM * KCOLS;        // (N, B, F, 45)

    const int smem_bytes = (48 + NGAUSS * GSTRIDE + NTUP * KCOLS +
                            NTUP * NL * BDIM + NTUP) * 4;
    int nblocks = (N + NBLK - 1) / NBLK;

    mega_kernel<<<nblocks, TPB, smem_bytes>>>(directs, weights,
                                              (const float4*)shapes, num_t,
                                              S, odf, ev, N);
}